// round 1
// baseline (speedup 1.0000x reference)
#include <cuda_runtime.h>

#define NB 64
#define C  64
#define T  256
#define V  25
#define S  3
#define R  8
#define O  64
#define TT 16
#define VP 28   // padded V for float4

// ---------------- scratch (device globals; no allocation) ----------------
__device__ float  g_xm[NB * C * V];              // 409600 floats
__device__ float  g_R[S * NB * O * V * V];       // 7,680,000 floats (~30.7MB)
__device__ float2 g_stats[O];

// ---------------- K1: xm[n,c,v] = mean_t x[n,c,t,v] ----------------
__global__ void k_xm(const float* __restrict__ x) {
    __shared__ float red[256 * V];
    int bx  = blockIdx.x;            // n*64 + c
    int tid = threadIdx.x;           // = t
    const float* row = x + (size_t)bx * T * V + (size_t)tid * V;
    #pragma unroll
    for (int v = 0; v < V; ++v) red[tid * V + v] = row[v];
    __syncthreads();
    for (int st = 128; st > 0; st >>= 1) {
        if (tid < st) {
            #pragma unroll
            for (int v = 0; v < V; ++v) red[tid * V + v] += red[(tid + st) * V + v];
        }
        __syncthreads();
    }
    if (tid < V) g_xm[bx * V + tid] = red[tid] * (1.0f / T);
}

// ---------------- K2: build R[s,n,o,u,v] ----------------
__global__ void k_R(const float* __restrict__ Ag,   const float* __restrict__ alphag,
                    const float* __restrict__ w1g,  const float* __restrict__ b1g,
                    const float* __restrict__ w2g,  const float* __restrict__ b2g,
                    const float* __restrict__ w4g,  const float* __restrict__ b4g,
                    const float* __restrict__ pw1g, const float* __restrict__ pb1g,
                    const float* __restrict__ pw2g, const float* __restrict__ pb2g,
                    const float* __restrict__ dwwg, const float* __restrict__ pjwg,
                    const float* __restrict__ betag,const float* __restrict__ gammag)
{
    extern __shared__ float sm[];
    float* q1s = sm;            // 5000 floats (reused as ta later)
    float* qas = sm + 5000;     // 5000
    float* ds  = sm + 10000;    // 5000
    float* x1s = sm + 15000;    // 200
    float* x2s = sm + 15200;    // 200
    float* as_ = sm + 15400;    // 200
    float* bs_ = sm + 15600;    // 200

    int n = blockIdx.x, s = blockIdx.y;
    int tid = threadIdx.x;
    const float* xm = g_xm + n * (C * V);

    // x1[r,u], x2[r,u]
    for (int idx = tid; idx < R * V; idx += blockDim.x) {
        int r = idx / V, u = idx % V;
        float s1 = b1g[s * R + r], s2 = b2g[s * R + r];
        const float* w1r = w1g + (s * R + r) * C;
        const float* w2r = w2g + (s * R + r) * C;
        for (int c = 0; c < C; ++c) {
            float xv = xm[c * V + u];
            s1 = fmaf(w1r[c], xv, s1);
            s2 = fmaf(w2r[c], xv, s2);
        }
        x1s[idx] = s1; x2s[idx] = s2;
    }
    __syncthreads();
    // a_[r,u] = sum_p pw1[r,p] x2[p,u] ; b_[r,v] = sum_p pw1[r,R+p] x2[p,v]
    for (int idx = tid; idx < R * V; idx += blockDim.x) {
        int r = idx / V, u = idx % V;
        const float* p1 = pw1g + (s * R + r) * (2 * R);
        float av = 0.f, bv = 0.f;
        #pragma unroll
        for (int p = 0; p < R; ++p) {
            av = fmaf(p1[p],     x2s[p * V + u], av);
            bv = fmaf(p1[R + p], x2s[p * V + u], bv);
        }
        as_[idx] = av; bs_[idx] = bv;
    }
    __syncthreads();
    // q1[r,u,v] = tanh(x1[r,u] - x2[r,v])
    for (int idx = tid; idx < R * V * V; idx += blockDim.x) {
        int r = idx / (V * V), uv = idx % (V * V), u = uv / V, v = uv % V;
        q1s[idx] = tanhf(x1s[r * V + u] - x2s[r * V + v]);
    }
    __syncthreads();
    // qall = q1 + gamma * (pw2 @ relu(a+b+pb1) + pb2)
    float gma = gammag[s];
    for (int uv = tid; uv < V * V; uv += blockDim.x) {
        int u = uv / V, v = uv % V;
        float h[R];
        #pragma unroll
        for (int p = 0; p < R; ++p)
            h[p] = fmaxf(as_[p * V + u] + bs_[p * V + v] + pb1g[s * R + p], 0.f);
        #pragma unroll
        for (int r = 0; r < R; ++r) {
            float q2 = pb2g[s * R + r];
            const float* p2 = pw2g + (s * R + r) * R;
            #pragma unroll
            for (int p = 0; p < R; ++p) q2 = fmaf(p2[p], h[p], q2);
            qas[r * V * V + uv] = q1s[r * V * V + uv] + gma * q2;
        }
    }
    __syncthreads();
    // depthwise 3x3 cross-correlation on q1 (zero pad)
    for (int idx = tid; idx < R * V * V; idx += blockDim.x) {
        int r = idx / (V * V), uv = idx % (V * V), u = uv / V, v = uv % V;
        const float* kw = dwwg + (s * R + r) * 9;
        float acc = 0.f;
        #pragma unroll
        for (int ki = 0; ki < 3; ++ki) {
            int uu = u + ki - 1; if (uu < 0 || uu >= V) continue;
            #pragma unroll
            for (int kj = 0; kj < 3; ++kj) {
                int vv = v + kj - 1; if (vv < 0 || vv >= V) continue;
                acc = fmaf(q1s[r * V * V + uu * V + vv], kw[ki * 3 + kj], acc);
            }
        }
        ds[idx] = acc;
    }
    __syncthreads();
    // 3x3 avgpool (count_include_pad) + tanh  -> ta (reuses q1 buffer)
    for (int idx = tid; idx < R * V * V; idx += blockDim.x) {
        int r = idx / (V * V), uv = idx % (V * V), u = uv / V, v = uv % V;
        float acc = 0.f;
        for (int ki = -1; ki <= 1; ++ki) {
            int uu = u + ki; if (uu < 0 || uu >= V) continue;
            for (int kj = -1; kj <= 1; ++kj) {
                int vv = v + kj; if (vv < 0 || vv >= V) continue;
                acc += ds[r * V * V + uu * V + vv];
            }
        }
        q1s[idx] = tanhf(acc * (1.f / 9.f));
    }
    __syncthreads();
    // R[o,u,v] = alpha*(w4@qall + b4) + A + beta*(pjw@ta)
    float alpha = alphag[0], beta = betag[s];
    const float* ta = q1s;
    for (int idx = tid; idx < O * V * V; idx += blockDim.x) {
        int o = idx / (V * V), uv = idx % (V * V);
        float a1 = b4g[s * O + o], a2 = 0.f;
        const float* w4r = w4g + (s * O + o) * R;
        const float* pjr = pjwg + (s * O + o) * R;
        #pragma unroll
        for (int r = 0; r < R; ++r) {
            a1 = fmaf(w4r[r], qas[r * V * V + uv], a1);
            a2 = fmaf(pjr[r], ta[r * V * V + uv], a2);
        }
        g_R[((size_t)(s * NB + n) * O + o) * (V * V) + uv]
            = fmaf(alpha, a1, Ag[s * V * V + uv]) + beta * a2;
    }
}

// ---------------- K3: fused x3-GEMM + R-apply, sum over branches ----------------
// smem layout (floats):
constexpr int XS_F = C * TT * VP;     // 28672 : x tile [c][t][VP]
constexpr int WS_F = XS_F;            // 28672 : w3^T [c][o]   (4096)
constexpr int B3_F = WS_F + C * O;    // 32768 : b3 (64)
constexpr int RS_F = B3_F + O;        // 32832 : R chunk [32][627]
constexpr int RSTR = 627;
constexpr int K3_SMEM_F = RS_F + 32 * RSTR;   // 52896 floats
constexpr int K3_SMEM_B = K3_SMEM_F * 4;      // 211584 bytes

__global__ void __launch_bounds__(512, 1) k_main(const float* __restrict__ x,
                                                 const float* __restrict__ w3g,
                                                 const float* __restrict__ b3g,
                                                 float* __restrict__ ybuf)
{
    extern __shared__ float sm[];
    int n = blockIdx.y, t0 = blockIdx.x * TT;
    int tid = threadIdx.x, wid = tid >> 5, lane = tid & 31;

    // load x tile: xs[c][t][0..24], pad 25..27 = 0
    for (int row = tid; row < C * TT; row += 512) {
        int c = row / TT, t = row % TT;
        const float* src = x + (((size_t)(n * C + c)) * T + t0 + t) * V;
        float* dst = sm + row * VP;
        #pragma unroll
        for (int v = 0; v < V; ++v) dst[v] = src[v];
        dst[25] = 0.f; dst[26] = 0.f; dst[27] = 0.f;
    }

    float z[2][25];
    #pragma unroll
    for (int j = 0; j < 2; ++j)
        #pragma unroll
        for (int u = 0; u < 25; ++u) z[j][u] = 0.f;

    int t = wid;  // 16 warps <-> 16 t positions

    #pragma unroll 1
    for (int s = 0; s < S; ++s) {
        __syncthreads();
        // w3^T into smem: wsT[c][o]
        for (int idx = tid; idx < C * O; idx += 512) {
            int c = idx >> 6, o = idx & 63;
            sm[WS_F + idx] = w3g[s * C * O + o * C + c];
        }
        if (tid < O) sm[B3_F + tid] = b3g[s * O + tid];

        #pragma unroll
        for (int och = 0; och < 2; ++och) {
            __syncthreads();
            {
                const float* Rg = g_R + ((size_t)(s * NB + n) * O + och * 32) * (V * V);
                for (int idx = tid; idx < 32 * 625; idx += 512) {
                    int oi = idx / 625, uv = idx % 625;
                    sm[RS_F + oi * RSTR + uv] = Rg[oi * 625 + uv];
                }
            }
            __syncthreads();

            int o = och * 32 + lane;
            float bb = sm[B3_F + o];
            float x3[VP];
            #pragma unroll
            for (int v = 0; v < VP; ++v) x3[v] = bb;

            #pragma unroll 1
            for (int c = 0; c < C; ++c) {
                float w = sm[WS_F + (c << 6) + o];                    // conflict-free
                const float4* xr = reinterpret_cast<const float4*>(sm + (c * TT + t) * VP); // broadcast
                #pragma unroll
                for (int k = 0; k < 7; ++k) {
                    float4 q = xr[k];
                    x3[4 * k + 0] = fmaf(q.x, w, x3[4 * k + 0]);
                    x3[4 * k + 1] = fmaf(q.y, w, x3[4 * k + 1]);
                    x3[4 * k + 2] = fmaf(q.z, w, x3[4 * k + 2]);
                    x3[4 * k + 3] = fmaf(q.w, w, x3[4 * k + 3]);
                }
            }
            const float* Rrow = sm + RS_F + lane * RSTR;              // conflict-free (627%32=19)
            #pragma unroll
            for (int u = 0; u < 25; ++u) {
                float acc = z[och][u];
                #pragma unroll
                for (int v = 0; v < 25; ++v)
                    acc = fmaf(x3[v], Rrow[u * 25 + v], acc);
                z[och][u] = acc;
            }
        }
    }

    // stage z through smem (stride 401, conflict-free) for coalesced store
    __syncthreads();
    #pragma unroll
    for (int och = 0; och < 2; ++och) {
        int o = och * 32 + lane;
        #pragma unroll
        for (int u = 0; u < 25; ++u)
            sm[o * 401 + t * V + u] = z[och][u];
    }
    __syncthreads();
    for (int idx = tid; idx < O * TT * V; idx += 512) {
        int o = idx / (TT * V), tu = idx % (TT * V);
        ybuf[((size_t)(n * O + o) * T + t0) * V + tu] = sm[o * 401 + tu];
    }
}

// ---------------- K4: BN batch stats per channel ----------------
__global__ void k_stats(const float* __restrict__ ybuf,
                        const float* __restrict__ bnw, const float* __restrict__ bnb)
{
    __shared__ float rs[512], rs2[512];
    int o = blockIdx.x, tid = threadIdx.x;
    float s = 0.f, s2 = 0.f;
    for (int n = 0; n < NB; ++n) {
        const float* base = ybuf + ((size_t)(n * O + o)) * T * V;
        for (int i = tid; i < T * V; i += 512) {
            float v = base[i];
            s += v; s2 = fmaf(v, v, s2);
        }
    }
    rs[tid] = s; rs2[tid] = s2;
    __syncthreads();
    for (int st = 256; st > 0; st >>= 1) {
        if (tid < st) { rs[tid] += rs[tid + st]; rs2[tid] += rs2[tid + st]; }
        __syncthreads();
    }
    if (tid == 0) {
        float M = (float)(NB * T * V);
        float mean = rs[0] / M;
        float var  = rs2[0] / M - mean * mean;
        float sc = bnw[o] * rsqrtf(var + 1e-5f);
        g_stats[o] = make_float2(sc, bnb[o] - mean * sc);
    }
}

// ---------------- K5: BN apply + residual + relu (in place) ----------------
__global__ void k_final(float* __restrict__ ybuf, const float* __restrict__ x)
{
    int idx = blockIdx.x * 512 + threadIdx.x;
    int o = (idx / (T * V)) & 63;
    float2 ss = g_stats[o];
    float v = fmaf(ybuf[idx], ss.x, ss.y) + x[idx];
    ybuf[idx] = fmaxf(v, 0.f);
}

// ---------------- launch ----------------
extern "C" void kernel_launch(void* const* d_in, const int* in_sizes, int n_in,
                              void* d_out, int out_size)
{
    (void)in_sizes; (void)n_in; (void)out_size;
    const float* x    = (const float*)d_in[0];
    const float* A    = (const float*)d_in[1];
    const float* alph = (const float*)d_in[2];
    const float* w1   = (const float*)d_in[3];
    const float* b1   = (const float*)d_in[4];
    const float* w2   = (const float*)d_in[5];
    const float* b2   = (const float*)d_in[6];
    const float* w3   = (const float*)d_in[7];
    const float* b3   = (const float*)d_in[8];
    const float* w4   = (const float*)d_in[9];
    const float* b4   = (const float*)d_in[10];
    const float* pw1  = (const float*)d_in[11];
    const float* pb1  = (const float*)d_in[12];
    const float* pw2  = (const float*)d_in[13];
    const float* pb2  = (const float*)d_in[14];
    const float* dww  = (const float*)d_in[15];
    const float* pjw  = (const float*)d_in[16];
    const float* beta = (const float*)d_in[17];
    const float* gamma= (const float*)d_in[18];
    const float* bnw  = (const float*)d_in[19];
    const float* bnb  = (const float*)d_in[20];
    float* out = (float*)d_out;

    cudaFuncSetAttribute(k_main, cudaFuncAttributeMaxDynamicSharedMemorySize, K3_SMEM_B);
    cudaFuncSetAttribute(k_R,    cudaFuncAttributeMaxDynamicSharedMemorySize, 15800 * 4);

    k_xm<<<NB * C, 256>>>(x);
    k_R<<<dim3(NB, S), 256, 15800 * 4>>>(A, alph, w1, b1, w2, b2, w4, b4,
                                         pw1, pb1, pw2, pb2, dww, pjw, beta, gamma);
    k_main<<<dim3(T / TT, NB), 512, K3_SMEM_B>>>(x, w3, b3, out);
    k_stats<<<O, 512>>>(out, bnw, bnb);
    k_final<<<(NB * C * T * V) / 512, 512>>>(out, x);
}

// round 2
// speedup vs baseline: 1.1088x; 1.1088x over previous
#include <cuda_runtime.h>

#define NB 64
#define C  64
#define T  256
#define V  25
#define S  3
#define R  8
#define O  64
#define TT 16

typedef unsigned long long ull;

// ---------------- scratch ----------------
__device__ float  g_xm[NB * C * V];
__device__ float  g_R[S * NB * O * V * V];       // ~30.7MB, fits L2
__device__ float2 g_stats[O];
__device__ float2 g_part[O * 8];

// ---------------- f32x2 helpers ----------------
__device__ __forceinline__ ull pk(float lo, float hi) {
    ull r; asm("mov.b64 %0, {%1,%2};" : "=l"(r) : "f"(lo), "f"(hi)); return r;
}
__device__ __forceinline__ void upk(float& lo, float& hi, ull v) {
    asm("mov.b64 {%0,%1}, %2;" : "=f"(lo), "=f"(hi) : "l"(v));
}
__device__ __forceinline__ ull f2fma(ull a, ull b, ull c) {
    ull d; asm("fma.rn.f32x2 %0, %1, %2, %3;" : "=l"(d) : "l"(a), "l"(b), "l"(c)); return d;
}

// ---------------- K1: xm[n,c,v] = mean_t x ----------------
__global__ void k_xm(const float* __restrict__ x) {
    __shared__ float red[256 * V];
    int bx  = blockIdx.x;
    int tid = threadIdx.x;
    const float* row = x + (size_t)bx * T * V + (size_t)tid * V;
    #pragma unroll
    for (int v = 0; v < V; ++v) red[tid * V + v] = row[v];
    __syncthreads();
    for (int st = 128; st > 0; st >>= 1) {
        if (tid < st) {
            #pragma unroll
            for (int v = 0; v < V; ++v) red[tid * V + v] += red[(tid + st) * V + v];
        }
        __syncthreads();
    }
    if (tid < V) g_xm[bx * V + tid] = red[tid] * (1.0f / T);
}

// ---------------- K2: build R[s,n,o,u,v] ----------------
__global__ void k_R(const float* __restrict__ Ag,   const float* __restrict__ alphag,
                    const float* __restrict__ w1g,  const float* __restrict__ b1g,
                    const float* __restrict__ w2g,  const float* __restrict__ b2g,
                    const float* __restrict__ w4g,  const float* __restrict__ b4g,
                    const float* __restrict__ pw1g, const float* __restrict__ pb1g,
                    const float* __restrict__ pw2g, const float* __restrict__ pb2g,
                    const float* __restrict__ dwwg, const float* __restrict__ pjwg,
                    const float* __restrict__ betag,const float* __restrict__ gammag)
{
    extern __shared__ float sm[];
    float* q1s = sm;            // 5000 (reused as ta)
    float* qas = sm + 5000;     // 5000
    float* ds  = sm + 10000;    // 5000
    float* x1s = sm + 15000;    // 200
    float* x2s = sm + 15200;    // 200
    float* as_ = sm + 15400;    // 200
    float* bs_ = sm + 15600;    // 200

    int n = blockIdx.x, s = blockIdx.y;
    int tid = threadIdx.x;
    const float* xm = g_xm + n * (C * V);

    for (int idx = tid; idx < R * V; idx += blockDim.x) {
        int r = idx / V, u = idx % V;
        float s1 = b1g[s * R + r], s2 = b2g[s * R + r];
        const float* w1r = w1g + (s * R + r) * C;
        const float* w2r = w2g + (s * R + r) * C;
        for (int c = 0; c < C; ++c) {
            float xv = xm[c * V + u];
            s1 = fmaf(w1r[c], xv, s1);
            s2 = fmaf(w2r[c], xv, s2);
        }
        x1s[idx] = s1; x2s[idx] = s2;
    }
    __syncthreads();
    for (int idx = tid; idx < R * V; idx += blockDim.x) {
        int r = idx / V, u = idx % V;
        const float* p1 = pw1g + (s * R + r) * (2 * R);
        float av = 0.f, bv = 0.f;
        #pragma unroll
        for (int p = 0; p < R; ++p) {
            av = fmaf(p1[p],     x2s[p * V + u], av);
            bv = fmaf(p1[R + p], x2s[p * V + u], bv);
        }
        as_[idx] = av; bs_[idx] = bv;
    }
    __syncthreads();
    for (int idx = tid; idx < R * V * V; idx += blockDim.x) {
        int r = idx / (V * V), uv = idx % (V * V), u = uv / V, v = uv % V;
        q1s[idx] = tanhf(x1s[r * V + u] - x2s[r * V + v]);
    }
    __syncthreads();
    float gma = gammag[s];
    for (int uv = tid; uv < V * V; uv += blockDim.x) {
        int u = uv / V, v = uv % V;
        float h[R];
        #pragma unroll
        for (int p = 0; p < R; ++p)
            h[p] = fmaxf(as_[p * V + u] + bs_[p * V + v] + pb1g[s * R + p], 0.f);
        #pragma unroll
        for (int r = 0; r < R; ++r) {
            float q2 = pb2g[s * R + r];
            const float* p2 = pw2g + (s * R + r) * R;
            #pragma unroll
            for (int p = 0; p < R; ++p) q2 = fmaf(p2[p], h[p], q2);
            qas[r * V * V + uv] = q1s[r * V * V + uv] + gma * q2;
        }
    }
    __syncthreads();
    for (int idx = tid; idx < R * V * V; idx += blockDim.x) {
        int r = idx / (V * V), uv = idx % (V * V), u = uv / V, v = uv % V;
        const float* kw = dwwg + (s * R + r) * 9;
        float acc = 0.f;
        #pragma unroll
        for (int ki = 0; ki < 3; ++ki) {
            int uu = u + ki - 1; if (uu < 0 || uu >= V) continue;
            #pragma unroll
            for (int kj = 0; kj < 3; ++kj) {
                int vv = v + kj - 1; if (vv < 0 || vv >= V) continue;
                acc = fmaf(q1s[r * V * V + uu * V + vv], kw[ki * 3 + kj], acc);
            }
        }
        ds[idx] = acc;
    }
    __syncthreads();
    for (int idx = tid; idx < R * V * V; idx += blockDim.x) {
        int r = idx / (V * V), uv = idx % (V * V), u = uv / V, v = uv % V;
        float acc = 0.f;
        for (int ki = -1; ki <= 1; ++ki) {
            int uu = u + ki; if (uu < 0 || uu >= V) continue;
            for (int kj = -1; kj <= 1; ++kj) {
                int vv = v + kj; if (vv < 0 || vv >= V) continue;
                acc += ds[r * V * V + uu * V + vv];
            }
        }
        q1s[idx] = tanhf(acc * (1.f / 9.f));
    }
    __syncthreads();
    float alpha = alphag[0], beta = betag[s];
    const float* ta = q1s;
    for (int idx = tid; idx < O * V * V; idx += blockDim.x) {
        int o = idx / (V * V), uv = idx % (V * V);
        float a1 = b4g[s * O + o], a2 = 0.f;
        const float* w4r = w4g + (s * O + o) * R;
        const float* pjr = pjwg + (s * O + o) * R;
        #pragma unroll
        for (int r = 0; r < R; ++r) {
            a1 = fmaf(w4r[r], qas[r * V * V + uv], a1);
            a2 = fmaf(pjr[r], ta[r * V * V + uv], a2);
        }
        g_R[((size_t)(s * NB + n) * O + o) * (V * V) + uv]
            = fmaf(alpha, a1, Ag[s * V * V + uv]) + beta * a2;
    }
}

// ---------------- K3: fused x3-GEMM + R-apply ----------------
// smem (floats):
//  XS0: x tile packed [c][k(13)][wp(8)] float4 = (x[t0][2k], x[t1][2k], x[t0][2k+1], x[t1][2k+1])
//  WS0: w3 pairs [c][lane] float2 = (w3[o=lane][c], w3[o=lane+32][c])
//  B30: b3 pairs [lane] float2
//  RS0: R half  [o(64)][u(25)][14]   (o-stride 350 words -> conflict-free LDS.64)
constexpr int XS0 = 0;                        // 26624 floats
constexpr int WS0 = 26624;                    // 4096
constexpr int B30 = 30720;                    // 64
constexpr int RS0 = 30784;                    // 22400
constexpr int K3_SMEM_F = 53184;
constexpr int K3_SMEM_B = K3_SMEM_F * 4;      // 212736 bytes

__device__ __forceinline__ void contract_half_impl(
    const ull* __restrict__ x3p, int np,
    const float* __restrict__ Rb, float* __restrict__ zt0, float* __restrict__ zt1);

template <int NP>
__device__ __forceinline__ void contract_half(const ull* __restrict__ x3p,
                                              const float* __restrict__ Rb,
                                              float* __restrict__ zt0,
                                              float* __restrict__ zt1)
{
    // transpose t-packed -> v-packed per t
    ull a0[NP], a1[NP];
    #pragma unroll
    for (int j = 0; j < NP; ++j) {
        float p0, p1, q0, q1;
        upk(p0, p1, x3p[2 * j]);
        upk(q0, q1, x3p[2 * j + 1]);
        a0[j] = pk(p0, q0);
        a1[j] = pk(p1, q1);
    }
    #pragma unroll
    for (int u = 0; u < 25; ++u) {
        const ull* Rp = reinterpret_cast<const ull*>(Rb + u * 14);
        ull acc0 = 0ull, acc1 = 0ull;
        #pragma unroll
        for (int j = 0; j < NP; ++j) {
            ull r = Rp[j];
            acc0 = f2fma(a0[j], r, acc0);
            acc1 = f2fma(a1[j], r, acc1);
        }
        float e0, e1, f0, f1;
        upk(e0, e1, acc0);
        upk(f0, f1, acc1);
        zt0[u] += e0 + e1;
        zt1[u] += f0 + f1;
    }
}

__global__ void __launch_bounds__(256, 1) k_main(const float* __restrict__ x,
                                                 const float* __restrict__ w3g,
                                                 const float* __restrict__ b3g,
                                                 float* __restrict__ ybuf)
{
    extern __shared__ float sm[];
    int n = blockIdx.y, tb = blockIdx.x * TT;
    int tid = threadIdx.x, wid = tid >> 5, lane = tid & 31;

    // ---- fill packed x tile ----
    for (int idx = tid; idx < C * TT * 13; idx += 256) {
        int k = idx % 13;
        int t = (idx / 13) % TT;
        int c = idx / (13 * TT);
        const float* src = x + (((size_t)(n * C + c)) * T + tb + t) * V;
        float a = src[2 * k];
        float b = (k < 12) ? src[2 * k + 1] : 0.f;
        int w  = t & 7;
        int hi = t >> 3;
        float* dst = sm + XS0 + ((c * 13 + k) * 8 + w) * 4;
        dst[hi]     = a;
        dst[2 + hi] = b;
    }

    float z[2][2][25];
    #pragma unroll
    for (int a = 0; a < 2; ++a)
        #pragma unroll
        for (int b = 0; b < 2; ++b)
            #pragma unroll
            for (int u = 0; u < 25; ++u) z[a][b][u] = 0.f;

    const float* Rgn = g_R;  // base; per-s offset below

    #pragma unroll 1
    for (int s = 0; s < S; ++s) {
        __syncthreads();
        // w3 pairs + b3 pairs + R half A (v 0..13)
        for (int idx = tid; idx < C * 32; idx += 256) {
            int c = idx >> 5, l = idx & 31;
            sm[WS0 + c * 64 + 2 * l]     = w3g[(s * O + l) * C + c];
            sm[WS0 + c * 64 + 2 * l + 1] = w3g[(s * O + l + 32) * C + c];
        }
        if (tid < 32) {
            sm[B30 + 2 * tid]     = b3g[s * O + tid];
            sm[B30 + 2 * tid + 1] = b3g[s * O + tid + 32];
        }
        {
            const float* Rg = Rgn + ((size_t)(s * NB + n)) * O * (V * V);
            for (int idx = tid; idx < 22400; idx += 256) {
                int j = idx % 14;
                int u = (idx / 14) % 25;
                int o = idx / 350;
                sm[RS0 + o * 350 + u * 14 + j] = Rg[o * 625 + u * 25 + j];
            }
        }
        __syncthreads();

        float2 bb = *reinterpret_cast<const float2*>(sm + B30 + 2 * lane);
        ull bl = pk(bb.x, bb.x), bh = pk(bb.y, bb.y);

        // ---- phase A: x3 for v=0..13, both o ----
        {
            ull x3l[14], x3h[14];
            #pragma unroll
            for (int v = 0; v < 14; ++v) { x3l[v] = bl; x3h[v] = bh; }
            #pragma unroll 2
            for (int c = 0; c < C; ++c) {
                float2 wp = *reinterpret_cast<const float2*>(sm + WS0 + c * 64 + 2 * lane);
                ull wl = pk(wp.x, wp.x), wh = pk(wp.y, wp.y);
                const float* xb = sm + XS0 + (c * 13) * 32 + wid * 4;
                #pragma unroll
                for (int k = 0; k < 7; ++k) {
                    ulonglong2 qq = *reinterpret_cast<const ulonglong2*>(xb + k * 32);
                    x3l[2 * k]     = f2fma(qq.x, wl, x3l[2 * k]);
                    x3h[2 * k]     = f2fma(qq.x, wh, x3h[2 * k]);
                    x3l[2 * k + 1] = f2fma(qq.y, wl, x3l[2 * k + 1]);
                    x3h[2 * k + 1] = f2fma(qq.y, wh, x3h[2 * k + 1]);
                }
            }
            contract_half<7>(x3l, sm + RS0 + (size_t)lane * 350,        z[0][0], z[0][1]);
            contract_half<7>(x3h, sm + RS0 + (size_t)(32 + lane) * 350, z[1][0], z[1][1]);
        }

        __syncthreads();
        // R half B (v 14..24, j 11..13 zero)
        {
            const float* Rg = Rgn + ((size_t)(s * NB + n)) * O * (V * V);
            for (int idx = tid; idx < 22400; idx += 256) {
                int j = idx % 14;
                int u = (idx / 14) % 25;
                int o = idx / 350;
                sm[RS0 + o * 350 + u * 14 + j] =
                    (j < 11) ? Rg[o * 625 + u * 25 + 14 + j] : 0.f;
            }
        }
        __syncthreads();

        // ---- phase B: x3 for v=14..25 ----
        {
            ull x3l[12], x3h[12];
            #pragma unroll
            for (int v = 0; v < 12; ++v) { x3l[v] = bl; x3h[v] = bh; }
            #pragma unroll 2
            for (int c = 0; c < C; ++c) {
                float2 wp = *reinterpret_cast<const float2*>(sm + WS0 + c * 64 + 2 * lane);
                ull wl = pk(wp.x, wp.x), wh = pk(wp.y, wp.y);
                const float* xb = sm + XS0 + (c * 13) * 32 + wid * 4;
                #pragma unroll
                for (int k = 7; k < 13; ++k) {
                    ulonglong2 qq = *reinterpret_cast<const ulonglong2*>(xb + k * 32);
                    int b2 = k - 7;
                    x3l[2 * b2]     = f2fma(qq.x, wl, x3l[2 * b2]);
                    x3h[2 * b2]     = f2fma(qq.x, wh, x3h[2 * b2]);
                    x3l[2 * b2 + 1] = f2fma(qq.y, wl, x3l[2 * b2 + 1]);
                    x3h[2 * b2 + 1] = f2fma(qq.y, wh, x3h[2 * b2 + 1]);
                }
            }
            contract_half<6>(x3l, sm + RS0 + (size_t)lane * 350,        z[0][0], z[0][1]);
            contract_half<6>(x3h, sm + RS0 + (size_t)(32 + lane) * 350, z[1][0], z[1][1]);
        }
    }

    // ---- stage + coalesced store ----
    __syncthreads();
    #pragma unroll
    for (int och = 0; och < 2; ++och) {
        int o = och * 32 + lane;
        #pragma unroll
        for (int u = 0; u < 25; ++u) {
            sm[o * 401 + wid * 25 + u]       = z[och][0][u];
            sm[o * 401 + (wid + 8) * 25 + u] = z[och][1][u];
        }
    }
    __syncthreads();
    for (int idx = tid; idx < O * TT * V; idx += 256) {
        int o = idx / (TT * V), tu = idx % (TT * V);
        ybuf[((size_t)(n * O + o) * T + tb) * V + tu] = sm[o * 401 + tu];
    }
}

// ---------------- K4a/K4b: BN stats ----------------
__global__ void k_stats1(const float* __restrict__ ybuf)
{
    __shared__ float rs[256], rq[256];
    int o = blockIdx.x, chunk = blockIdx.y;
    int tid = threadIdx.x;
    float s = 0.f, s2 = 0.f;
    for (int nn = 0; nn < 8; ++nn) {
        const float* base = ybuf + ((size_t)((chunk * 8 + nn) * O + o)) * (T * V);
        for (int i = tid; i < T * V; i += 256) {
            float v = base[i];
            s += v; s2 = fmaf(v, v, s2);
        }
    }
    rs[tid] = s; rq[tid] = s2;
    __syncthreads();
    for (int st = 128; st > 0; st >>= 1) {
        if (tid < st) { rs[tid] += rs[tid + st]; rq[tid] += rq[tid + st]; }
        __syncthreads();
    }
    if (tid == 0) g_part[o * 8 + chunk] = make_float2(rs[0], rq[0]);
}

__global__ void k_stats2(const float* __restrict__ bnw, const float* __restrict__ bnb)
{
    int o = threadIdx.x;
    float s = 0.f, s2 = 0.f;
    for (int c = 0; c < 8; ++c) { float2 p = g_part[o * 8 + c]; s += p.x; s2 += p.y; }
    float M = (float)(NB * T * V);
    float mean = s / M;
    float var  = s2 / M - mean * mean;
    float sc = bnw[o] * rsqrtf(var + 1e-5f);
    g_stats[o] = make_float2(sc, bnb[o] - mean * sc);
}

// ---------------- K5: BN apply + residual + relu ----------------
__global__ void k_final(float4* __restrict__ ybuf, const float4* __restrict__ x)
{
    int idx = blockIdx.x * 256 + threadIdx.x;
    int o = (idx / (T * V / 4)) & 63;
    float2 ss = g_stats[o];
    float4 y = ybuf[idx], xx = x[idx];
    y.x = fmaxf(fmaf(y.x, ss.x, ss.y) + xx.x, 0.f);
    y.y = fmaxf(fmaf(y.y, ss.x, ss.y) + xx.y, 0.f);
    y.z = fmaxf(fmaf(y.z, ss.x, ss.y) + xx.z, 0.f);
    y.w = fmaxf(fmaf(y.w, ss.x, ss.y) + xx.w, 0.f);
    ybuf[idx] = y;
}

// ---------------- launch ----------------
extern "C" void kernel_launch(void* const* d_in, const int* in_sizes, int n_in,
                              void* d_out, int out_size)
{
    (void)in_sizes; (void)n_in; (void)out_size;
    const float* x    = (const float*)d_in[0];
    const float* A    = (const float*)d_in[1];
    const float* alph = (const float*)d_in[2];
    const float* w1   = (const float*)d_in[3];
    const float* b1   = (const float*)d_in[4];
    const float* w2   = (const float*)d_in[5];
    const float* b2   = (const float*)d_in[6];
    const float* w3   = (const float*)d_in[7];
    const float* b3   = (const float*)d_in[8];
    const float* w4   = (const float*)d_in[9];
    const float* b4   = (const float*)d_in[10];
    const float* pw1  = (const float*)d_in[11];
    const float* pb1  = (const float*)d_in[12];
    const float* pw2  = (const float*)d_in[13];
    const float* pb2  = (const float*)d_in[14];
    const float* dww  = (const float*)d_in[15];
    const float* pjw  = (const float*)d_in[16];
    const float* beta = (const float*)d_in[17];
    const float* gamma= (const float*)d_in[18];
    const float* bnw  = (const float*)d_in[19];
    const float* bnb  = (const float*)d_in[20];
    float* out = (float*)d_out;

    cudaFuncSetAttribute(k_main, cudaFuncAttributeMaxDynamicSharedMemorySize, K3_SMEM_B);
    cudaFuncSetAttribute(k_R,    cudaFuncAttributeMaxDynamicSharedMemorySize, 15800 * 4);

    k_xm<<<NB * C, 256>>>(x);
    k_R<<<dim3(NB, S), 256, 15800 * 4>>>(A, alph, w1, b1, w2, b2, w4, b4,
                                         pw1, pb1, pw2, pb2, dww, pjw, beta, gamma);
    k_main<<<dim3(T / TT, NB), 256, K3_SMEM_B>>>(x, w3, b3, out);
    k_stats1<<<dim3(O, 8), 256>>>(out);
    k_stats2<<<1, O>>>(bnw, bnb);
    k_final<<<(NB * C * T * V) / 1024, 256>>>((float4*)out, (const float4*)x);
}

// round 3
// speedup vs baseline: 1.3418x; 1.2101x over previous
#include <cuda_runtime.h>

#define NB 64
#define C  64
#define T  256
#define V  25
#define S  3
#define R  8
#define O  64
#define TT 16

typedef unsigned long long ull;

// ---------------- scratch ----------------
__device__ float  g_xm[NB * C * V];
__device__ float  g_R2[S * NB * 2 * 22400];      // padded/split R: [s][n][h][o*350+u*14+j]
__device__ float2 g_stats[O];
__device__ float2 g_part[O * 8];

// ---------------- f32x2 helpers ----------------
__device__ __forceinline__ ull pk(float lo, float hi) {
    ull r; asm("mov.b64 %0, {%1,%2};" : "=l"(r) : "f"(lo), "f"(hi)); return r;
}
__device__ __forceinline__ void upk(float& lo, float& hi, ull v) {
    asm("mov.b64 {%0,%1}, %2;" : "=f"(lo), "=f"(hi) : "l"(v));
}
__device__ __forceinline__ ull f2fma(ull a, ull b, ull c) {
    ull d; asm("fma.rn.f32x2 %0, %1, %2, %3;" : "=l"(d) : "l"(a), "l"(b), "l"(c)); return d;
}

// ---------------- K1: xm[n,c,v] = mean_t x ----------------
__global__ void k_xm(const float* __restrict__ x) {
    __shared__ float red[256 * V];
    int bx  = blockIdx.x;
    int tid = threadIdx.x;
    const float* row = x + (size_t)bx * T * V + (size_t)tid * V;
    #pragma unroll
    for (int v = 0; v < V; ++v) red[tid * V + v] = row[v];
    __syncthreads();
    for (int st = 128; st > 0; st >>= 1) {
        if (tid < st) {
            #pragma unroll
            for (int v = 0; v < V; ++v) red[tid * V + v] += red[(tid + st) * V + v];
        }
        __syncthreads();
    }
    if (tid < V) g_xm[bx * V + tid] = red[tid] * (1.0f / T);
}

// ---------------- K2: build padded/split R2 ----------------
__global__ void k_R(const float* __restrict__ Ag,   const float* __restrict__ alphag,
                    const float* __restrict__ w1g,  const float* __restrict__ b1g,
                    const float* __restrict__ w2g,  const float* __restrict__ b2g,
                    const float* __restrict__ w4g,  const float* __restrict__ b4g,
                    const float* __restrict__ pw1g, const float* __restrict__ pb1g,
                    const float* __restrict__ pw2g, const float* __restrict__ pb2g,
                    const float* __restrict__ dwwg, const float* __restrict__ pjwg,
                    const float* __restrict__ betag,const float* __restrict__ gammag)
{
    extern __shared__ float sm[];
    float* q1s = sm;            // 5000 (reused as ta)
    float* qas = sm + 5000;     // 5000
    float* ds  = sm + 10000;    // 5000
    float* x1s = sm + 15000;    // 200
    float* x2s = sm + 15200;    // 200
    float* as_ = sm + 15400;    // 200
    float* bs_ = sm + 15600;    // 200

    int n = blockIdx.x, s = blockIdx.y;
    int tid = threadIdx.x;
    const float* xm = g_xm + n * (C * V);

    for (int idx = tid; idx < R * V; idx += blockDim.x) {
        int r = idx / V, u = idx % V;
        float s1 = b1g[s * R + r], s2 = b2g[s * R + r];
        const float* w1r = w1g + (s * R + r) * C;
        const float* w2r = w2g + (s * R + r) * C;
        for (int c = 0; c < C; ++c) {
            float xv = xm[c * V + u];
            s1 = fmaf(w1r[c], xv, s1);
            s2 = fmaf(w2r[c], xv, s2);
        }
        x1s[idx] = s1; x2s[idx] = s2;
    }
    __syncthreads();
    for (int idx = tid; idx < R * V; idx += blockDim.x) {
        int r = idx / V, u = idx % V;
        const float* p1 = pw1g + (s * R + r) * (2 * R);
        float av = 0.f, bv = 0.f;
        #pragma unroll
        for (int p = 0; p < R; ++p) {
            av = fmaf(p1[p],     x2s[p * V + u], av);
            bv = fmaf(p1[R + p], x2s[p * V + u], bv);
        }
        as_[idx] = av; bs_[idx] = bv;
    }
    __syncthreads();
    for (int idx = tid; idx < R * V * V; idx += blockDim.x) {
        int r = idx / (V * V), uv = idx % (V * V), u = uv / V, v = uv % V;
        q1s[idx] = tanhf(x1s[r * V + u] - x2s[r * V + v]);
    }
    __syncthreads();
    float gma = gammag[s];
    for (int uv = tid; uv < V * V; uv += blockDim.x) {
        int u = uv / V, v = uv % V;
        float h[R];
        #pragma unroll
        for (int p = 0; p < R; ++p)
            h[p] = fmaxf(as_[p * V + u] + bs_[p * V + v] + pb1g[s * R + p], 0.f);
        #pragma unroll
        for (int r = 0; r < R; ++r) {
            float q2 = pb2g[s * R + r];
            const float* p2 = pw2g + (s * R + r) * R;
            #pragma unroll
            for (int p = 0; p < R; ++p) q2 = fmaf(p2[p], h[p], q2);
            qas[r * V * V + uv] = q1s[r * V * V + uv] + gma * q2;
        }
    }
    __syncthreads();
    for (int idx = tid; idx < R * V * V; idx += blockDim.x) {
        int r = idx / (V * V), uv = idx % (V * V), u = uv / V, v = uv % V;
        const float* kw = dwwg + (s * R + r) * 9;
        float acc = 0.f;
        #pragma unroll
        for (int ki = 0; ki < 3; ++ki) {
            int uu = u + ki - 1; if (uu < 0 || uu >= V) continue;
            #pragma unroll
            for (int kj = 0; kj < 3; ++kj) {
                int vv = v + kj - 1; if (vv < 0 || vv >= V) continue;
                acc = fmaf(q1s[r * V * V + uu * V + vv], kw[ki * 3 + kj], acc);
            }
        }
        ds[idx] = acc;
    }
    __syncthreads();
    for (int idx = tid; idx < R * V * V; idx += blockDim.x) {
        int r = idx / (V * V), uv = idx % (V * V), u = uv / V, v = uv % V;
        float acc = 0.f;
        for (int ki = -1; ki <= 1; ++ki) {
            int uu = u + ki; if (uu < 0 || uu >= V) continue;
            for (int kj = -1; kj <= 1; ++kj) {
                int vv = v + kj; if (vv < 0 || vv >= V) continue;
                acc += ds[r * V * V + uu * V + vv];
            }
        }
        q1s[idx] = tanhf(acc * (1.f / 9.f));
    }
    __syncthreads();
    // R2[h][o][u][j] : v = h*14 + j, padded with zeros (j>=14-h*3 range beyond v=24)
    float alpha = alphag[0], beta = betag[s];
    const float* ta = q1s;
    float* dst = g_R2 + ((size_t)(s * NB + n)) * 2 * 22400;
    for (int idx = tid; idx < 2 * 22400; idx += blockDim.x) {
        int h   = idx / 22400;
        int rem = idx % 22400;
        int o   = rem / 350;
        int uj  = rem % 350;
        int u   = uj / 14, j = uj % 14;
        int v   = h * 14 + j;
        float val = 0.f;
        if (v < V) {
            int uv = u * V + v;
            float a1 = b4g[s * O + o], a2 = 0.f;
            const float* w4r = w4g + (s * O + o) * R;
            const float* pjr = pjwg + (s * O + o) * R;
            #pragma unroll
            for (int r = 0; r < R; ++r) {
                a1 = fmaf(w4r[r], qas[r * V * V + uv], a1);
                a2 = fmaf(pjr[r], ta[r * V * V + uv], a2);
            }
            val = fmaf(alpha, a1, Ag[s * V * V + uv]) + beta * a2;
        }
        dst[idx] = val;
    }
}

// ---------------- K3: fused x3-GEMM + R-apply ----------------
// smem (floats):
//  XS0: x tile packed [c][k(13)][tp(8)] float4 = (x[t0][2k], x[t1][2k], x[t0][2k+1], x[t1][2k+1])
//       where t0 = tp, t1 = tp + 8
//  WS0: w3 [c][o]  (plain, 4096)
//  B30: b3 [o] (64)
//  RS0: R half [o(64)][u(25)][14]  (o-stride 350, conflict-free LDS.64)
constexpr int XS0 = 0;                        // 26624 floats
constexpr int WS0 = 26624;                    // 4096
constexpr int B30 = 30720;                    // 64
constexpr int RS0 = 30784;                    // 22400
constexpr int K3_SMEM_F = 53184;
constexpr int K3_SMEM_B = K3_SMEM_F * 4;      // 212736 bytes

template <int NP>
__device__ __forceinline__ void contract_half(const ull* __restrict__ x3p,
                                              const float* __restrict__ Rb,
                                              float* __restrict__ zt0,
                                              float* __restrict__ zt1)
{
    // transpose t-packed -> v-packed per t
    ull a0[NP], a1[NP];
    #pragma unroll
    for (int j = 0; j < NP; ++j) {
        float p0, p1, q0, q1;
        upk(p0, p1, x3p[2 * j]);
        upk(q0, q1, x3p[2 * j + 1]);
        a0[j] = pk(p0, q0);
        a1[j] = pk(p1, q1);
    }
    #pragma unroll
    for (int u = 0; u < 25; ++u) {
        const ull* Rp = reinterpret_cast<const ull*>(Rb + u * 14);
        ull acc0 = 0ull, acc1 = 0ull;
        #pragma unroll
        for (int j = 0; j < NP; ++j) {
            ull r = Rp[j];
            acc0 = f2fma(a0[j], r, acc0);
            acc1 = f2fma(a1[j], r, acc1);
        }
        float e0, e1, f0, f1;
        upk(e0, e1, acc0);
        upk(f0, f1, acc1);
        zt0[u] += e0 + e1;
        zt1[u] += f0 + f1;
    }
}

__global__ void __launch_bounds__(512, 1) k_main(const float* __restrict__ x,
                                                 const float* __restrict__ w3g,
                                                 const float* __restrict__ b3g,
                                                 float* __restrict__ ybuf)
{
    extern __shared__ float sm[];
    int n = blockIdx.y, tb = blockIdx.x * TT;
    int tid = threadIdx.x, wid = tid >> 5, lane = tid & 31;
    int tp  = wid & 7;          // t-pair index: t0 = tp, t1 = tp + 8
    int och = wid >> 3;         // o-chunk: o = och*32 + lane

    // ---- fill packed x tile ----
    for (int idx = tid; idx < C * TT * 13; idx += 512) {
        int k = idx % 13;
        int t = (idx / 13) % TT;
        int c = idx / (13 * TT);
        const float* src = x + (((size_t)(n * C + c)) * T + tb + t) * V;
        float a = src[2 * k];
        float b = (k < 12) ? src[2 * k + 1] : 0.f;
        int w  = t & 7;
        int hi = t >> 3;
        float* dst = sm + XS0 + ((c * 13 + k) * 8 + w) * 4;
        dst[hi]     = a;
        dst[2 + hi] = b;
    }

    float z[2][25];
    #pragma unroll
    for (int b = 0; b < 2; ++b)
        #pragma unroll
        for (int u = 0; u < 25; ++u) z[b][u] = 0.f;

    int o = och * 32 + lane;

    #pragma unroll 1
    for (int s = 0; s < S; ++s) {
        __syncthreads();
        // w3 + b3 + R half A (float4 streaming copy)
        for (int idx = tid; idx < C * O; idx += 512) {
            int c = idx >> 6, oo = idx & 63;
            sm[WS0 + idx] = w3g[(s * O + oo) * C + c];
        }
        if (tid < O) sm[B30 + tid] = b3g[s * O + tid];
        {
            const float4* Rg = reinterpret_cast<const float4*>(
                g_R2 + ((size_t)(s * NB + n)) * 2 * 22400);
            float4* Rd = reinterpret_cast<float4*>(sm + RS0);
            for (int idx = tid; idx < 5600; idx += 512) Rd[idx] = Rg[idx];
        }
        __syncthreads();

        float bbs = sm[B30 + o];
        ull  bl   = pk(bbs, bbs);

        // ---- phase A: x3 for v=0..13 ----
        {
            ull x3p[14];
            #pragma unroll
            for (int v = 0; v < 14; ++v) x3p[v] = bl;
            #pragma unroll 2
            for (int c = 0; c < C; ++c) {
                float wv = sm[WS0 + (c << 6) + o];
                ull wl = pk(wv, wv);
                const float* xb = sm + XS0 + (c * 13) * 32 + tp * 4;
                #pragma unroll
                for (int k = 0; k < 7; ++k) {
                    ulonglong2 qq = *reinterpret_cast<const ulonglong2*>(xb + k * 32);
                    x3p[2 * k]     = f2fma(qq.x, wl, x3p[2 * k]);
                    x3p[2 * k + 1] = f2fma(qq.y, wl, x3p[2 * k + 1]);
                }
            }
            contract_half<7>(x3p, sm + RS0 + (size_t)o * 350, z[0], z[1]);
        }

        __syncthreads();
        // R half B (float4 streaming copy)
        {
            const float4* Rg = reinterpret_cast<const float4*>(
                g_R2 + ((size_t)(s * NB + n)) * 2 * 22400 + 22400);
            float4* Rd = reinterpret_cast<float4*>(sm + RS0);
            for (int idx = tid; idx < 5600; idx += 512) Rd[idx] = Rg[idx];
        }
        __syncthreads();

        // ---- phase B: x3 for v=14..24 ----
        {
            ull x3p[12];
            #pragma unroll
            for (int v = 0; v < 12; ++v) x3p[v] = bl;
            #pragma unroll 2
            for (int c = 0; c < C; ++c) {
                float wv = sm[WS0 + (c << 6) + o];
                ull wl = pk(wv, wv);
                const float* xb = sm + XS0 + (c * 13) * 32 + tp * 4;
                #pragma unroll
                for (int k = 7; k < 13; ++k) {
                    ulonglong2 qq = *reinterpret_cast<const ulonglong2*>(xb + k * 32);
                    int b2 = k - 7;
                    x3p[2 * b2]     = f2fma(qq.x, wl, x3p[2 * b2]);
                    x3p[2 * b2 + 1] = f2fma(qq.y, wl, x3p[2 * b2 + 1]);
                }
            }
            contract_half<6>(x3p, sm + RS0 + (size_t)o * 350, z[0], z[1]);
        }
    }

    // ---- stage + coalesced store ----
    __syncthreads();
    #pragma unroll
    for (int u = 0; u < 25; ++u) {
        sm[o * 401 + tp * 25 + u]       = z[0][u];
        sm[o * 401 + (tp + 8) * 25 + u] = z[1][u];
    }
    __syncthreads();
    for (int idx = tid; idx < O * TT * V; idx += 512) {
        int oo = idx / (TT * V), tu = idx % (TT * V);
        ybuf[((size_t)(n * O + oo) * T + tb) * V + tu] = sm[oo * 401 + tu];
    }
}

// ---------------- K4a/K4b: BN stats ----------------
__global__ void k_stats1(const float* __restrict__ ybuf)
{
    __shared__ float rs[256], rq[256];
    int o = blockIdx.x, chunk = blockIdx.y;
    int tid = threadIdx.x;
    float s = 0.f, s2 = 0.f;
    for (int nn = 0; nn < 8; ++nn) {
        const float* base = ybuf + ((size_t)((chunk * 8 + nn) * O + o)) * (T * V);
        for (int i = tid; i < T * V; i += 256) {
            float v = base[i];
            s += v; s2 = fmaf(v, v, s2);
        }
    }
    rs[tid] = s; rq[tid] = s2;
    __syncthreads();
    for (int st = 128; st > 0; st >>= 1) {
        if (tid < st) { rs[tid] += rs[tid + st]; rq[tid] += rq[tid + st]; }
        __syncthreads();
    }
    if (tid == 0) g_part[o * 8 + chunk] = make_float2(rs[0], rq[0]);
}

__global__ void k_stats2(const float* __restrict__ bnw, const float* __restrict__ bnb)
{
    int o = threadIdx.x;
    float s = 0.f, s2 = 0.f;
    for (int c = 0; c < 8; ++c) { float2 p = g_part[o * 8 + c]; s += p.x; s2 += p.y; }
    float M = (float)(NB * T * V);
    float mean = s / M;
    float var  = s2 / M - mean * mean;
    float sc = bnw[o] * rsqrtf(var + 1e-5f);
    g_stats[o] = make_float2(sc, bnb[o] - mean * sc);
}

// ---------------- K5: BN apply + residual + relu ----------------
__global__ void k_final(float4* __restrict__ ybuf, const float4* __restrict__ x)
{
    int idx = blockIdx.x * 256 + threadIdx.x;
    int o = (idx / (T * V / 4)) & 63;
    float2 ss = g_stats[o];
    float4 y = ybuf[idx], xx = x[idx];
    y.x = fmaxf(fmaf(y.x, ss.x, ss.y) + xx.x, 0.f);
    y.y = fmaxf(fmaf(y.y, ss.x, ss.y) + xx.y, 0.f);
    y.z = fmaxf(fmaf(y.z, ss.x, ss.y) + xx.z, 0.f);
    y.w = fmaxf(fmaf(y.w, ss.x, ss.y) + xx.w, 0.f);
    ybuf[idx] = y;
}

// ---------------- launch ----------------
extern "C" void kernel_launch(void* const* d_in, const int* in_sizes, int n_in,
                              void* d_out, int out_size)
{
    (void)in_sizes; (void)n_in; (void)out_size;
    const float* x    = (const float*)d_in[0];
    const float* A    = (const float*)d_in[1];
    const float* alph = (const float*)d_in[2];
    const float* w1   = (const float*)d_in[3];
    const float* b1   = (const float*)d_in[4];
    const float* w2   = (const float*)d_in[5];
    const float* b2   = (const float*)d_in[6];
    const float* w3   = (const float*)d_in[7];
    const float* b3   = (const float*)d_in[8];
    const float* w4   = (const float*)d_in[9];
    const float* b4   = (const float*)d_in[10];
    const float* pw1  = (const float*)d_in[11];
    const float* pb1  = (const float*)d_in[12];
    const float* pw2  = (const float*)d_in[13];
    const float* pb2  = (const float*)d_in[14];
    const float* dww  = (const float*)d_in[15];
    const float* pjw  = (const float*)d_in[16];
    const float* beta = (const float*)d_in[17];
    const float* gamma= (const float*)d_in[18];
    const float* bnw  = (const float*)d_in[19];
    const float* bnb  = (const float*)d_in[20];
    float* out = (float*)d_out;

    cudaFuncSetAttribute(k_main, cudaFuncAttributeMaxDynamicSharedMemorySize, K3_SMEM_B);
    cudaFuncSetAttribute(k_R,    cudaFuncAttributeMaxDynamicSharedMemorySize, 15800 * 4);

    k_xm<<<NB * C, 256>>>(x);
    k_R<<<dim3(NB, S), 256, 15800 * 4>>>(A, alph, w1, b1, w2, b2, w4, b4,
                                         pw1, pb1, pw2, pb2, dww, pjw, beta, gamma);
    k_main<<<dim3(T / TT, NB), 512, K3_SMEM_B>>>(x, w3, b3, out);
    k_stats1<<<dim3(O, 8), 256>>>(out);
    k_stats2<<<1, O>>>(bnw, bnb);
    k_final<<<(NB * C * T * V) / 1024, 256>>>((float4*)out, (const float4*)x);
}

// round 4
// speedup vs baseline: 1.3911x; 1.0367x over previous
#include <cuda_runtime.h>

#define NB 64
#define C  64
#define T  256
#define V  25
#define S  3
#define R  8
#define O  64
#define TT 16

typedef unsigned long long ull;

// ---------------- scratch ----------------
__device__ float  g_xm[NB * C * V];
__device__ float  g_R2[S * NB * 2 * 22400];      // padded/split R: [s][n][h][o*350+u*14+j]
__device__ float  g_w3t[S * C * O];              // w3 transposed: [s][c][o]
__device__ float2 g_stats[O];
__device__ float2 g_part[O * 16];

// ---------------- f32x2 helpers ----------------
__device__ __forceinline__ ull pk(float lo, float hi) {
    ull r; asm("mov.b64 %0, {%1,%2};" : "=l"(r) : "f"(lo), "f"(hi)); return r;
}
__device__ __forceinline__ void upk(float& lo, float& hi, ull v) {
    asm("mov.b64 {%0,%1}, %2;" : "=f"(lo), "=f"(hi) : "l"(v));
}
__device__ __forceinline__ ull f2fma(ull a, ull b, ull c) {
    ull d; asm("fma.rn.f32x2 %0, %1, %2, %3;" : "=l"(d) : "l"(a), "l"(b), "l"(c)); return d;
}

// ---------------- K1: xm[n,c,v] = mean_t x ----------------
__global__ void k_xm(const float* __restrict__ x) {
    __shared__ float red[256 * V];
    int bx  = blockIdx.x;
    int tid = threadIdx.x;
    const float* row = x + (size_t)bx * T * V + (size_t)tid * V;
    #pragma unroll
    for (int v = 0; v < V; ++v) red[tid * V + v] = row[v];
    __syncthreads();
    for (int st = 128; st > 0; st >>= 1) {
        if (tid < st) {
            #pragma unroll
            for (int v = 0; v < V; ++v) red[tid * V + v] += red[(tid + st) * V + v];
        }
        __syncthreads();
    }
    if (tid < V) g_xm[bx * V + tid] = red[tid] * (1.0f / T);
}

// ---------------- K1b: transpose w3 -> [s][c][o] ----------------
__global__ void k_w3t(const float* __restrict__ w3g) {
    int idx = blockIdx.x * 256 + threadIdx.x;     // s*4096 + c*64 + o
    int s = idx >> 12, co = idx & 4095, c = co >> 6, o = co & 63;
    g_w3t[idx] = w3g[(s * O + o) * C + c];
}

// ---------------- K2: build padded/split R2 ----------------
__global__ void k_R(const float* __restrict__ Ag,   const float* __restrict__ alphag,
                    const float* __restrict__ w1g,  const float* __restrict__ b1g,
                    const float* __restrict__ w2g,  const float* __restrict__ b2g,
                    const float* __restrict__ w4g,  const float* __restrict__ b4g,
                    const float* __restrict__ pw1g, const float* __restrict__ pb1g,
                    const float* __restrict__ pw2g, const float* __restrict__ pb2g,
                    const float* __restrict__ dwwg, const float* __restrict__ pjwg,
                    const float* __restrict__ betag,const float* __restrict__ gammag)
{
    extern __shared__ float sm[];
    float* q1s = sm;            // 5000 (reused as ta)
    float* qas = sm + 5000;     // 5000
    float* ds  = sm + 10000;    // 5000
    float* x1s = sm + 15000;    // 200
    float* x2s = sm + 15200;    // 200
    float* as_ = sm + 15400;    // 200
    float* bs_ = sm + 15600;    // 200

    int n = blockIdx.x, s = blockIdx.y;
    int tid = threadIdx.x;
    const float* xm = g_xm + n * (C * V);

    for (int idx = tid; idx < R * V; idx += blockDim.x) {
        int r = idx / V, u = idx % V;
        float s1 = b1g[s * R + r], s2 = b2g[s * R + r];
        const float* w1r = w1g + (s * R + r) * C;
        const float* w2r = w2g + (s * R + r) * C;
        for (int c = 0; c < C; ++c) {
            float xv = xm[c * V + u];
            s1 = fmaf(w1r[c], xv, s1);
            s2 = fmaf(w2r[c], xv, s2);
        }
        x1s[idx] = s1; x2s[idx] = s2;
    }
    __syncthreads();
    for (int idx = tid; idx < R * V; idx += blockDim.x) {
        int r = idx / V, u = idx % V;
        const float* p1 = pw1g + (s * R + r) * (2 * R);
        float av = 0.f, bv = 0.f;
        #pragma unroll
        for (int p = 0; p < R; ++p) {
            av = fmaf(p1[p],     x2s[p * V + u], av);
            bv = fmaf(p1[R + p], x2s[p * V + u], bv);
        }
        as_[idx] = av; bs_[idx] = bv;
    }
    __syncthreads();
    for (int idx = tid; idx < R * V * V; idx += blockDim.x) {
        int r = idx / (V * V), uv = idx % (V * V), u = uv / V, v = uv % V;
        q1s[idx] = tanhf(x1s[r * V + u] - x2s[r * V + v]);
    }
    __syncthreads();
    float gma = gammag[s];
    for (int uv = tid; uv < V * V; uv += blockDim.x) {
        int u = uv / V, v = uv % V;
        float h[R];
        #pragma unroll
        for (int p = 0; p < R; ++p)
            h[p] = fmaxf(as_[p * V + u] + bs_[p * V + v] + pb1g[s * R + p], 0.f);
        #pragma unroll
        for (int r = 0; r < R; ++r) {
            float q2 = pb2g[s * R + r];
            const float* p2 = pw2g + (s * R + r) * R;
            #pragma unroll
            for (int p = 0; p < R; ++p) q2 = fmaf(p2[p], h[p], q2);
            qas[r * V * V + uv] = q1s[r * V * V + uv] + gma * q2;
        }
    }
    __syncthreads();
    for (int idx = tid; idx < R * V * V; idx += blockDim.x) {
        int r = idx / (V * V), uv = idx % (V * V), u = uv / V, v = uv % V;
        const float* kw = dwwg + (s * R + r) * 9;
        float acc = 0.f;
        #pragma unroll
        for (int ki = 0; ki < 3; ++ki) {
            int uu = u + ki - 1; if (uu < 0 || uu >= V) continue;
            #pragma unroll
            for (int kj = 0; kj < 3; ++kj) {
                int vv = v + kj - 1; if (vv < 0 || vv >= V) continue;
                acc = fmaf(q1s[r * V * V + uu * V + vv], kw[ki * 3 + kj], acc);
            }
        }
        ds[idx] = acc;
    }
    __syncthreads();
    for (int idx = tid; idx < R * V * V; idx += blockDim.x) {
        int r = idx / (V * V), uv = idx % (V * V), u = uv / V, v = uv % V;
        float acc = 0.f;
        for (int ki = -1; ki <= 1; ++ki) {
            int uu = u + ki; if (uu < 0 || uu >= V) continue;
            for (int kj = -1; kj <= 1; ++kj) {
                int vv = v + kj; if (vv < 0 || vv >= V) continue;
                acc += ds[r * V * V + uu * V + vv];
            }
        }
        q1s[idx] = tanhf(acc * (1.f / 9.f));
    }
    __syncthreads();
    float alpha = alphag[0], beta = betag[s];
    const float* ta = q1s;
    float* dst = g_R2 + ((size_t)(s * NB + n)) * 2 * 22400;
    for (int idx = tid; idx < 2 * 22400; idx += blockDim.x) {
        int h   = idx / 22400;
        int rem = idx % 22400;
        int o   = rem / 350;
        int uj  = rem % 350;
        int u   = uj / 14, j = uj % 14;
        int v   = h * 14 + j;
        float val = 0.f;
        if (v < V) {
            int uv = u * V + v;
            float a1 = b4g[s * O + o], a2 = 0.f;
            const float* w4r = w4g + (s * O + o) * R;
            const float* pjr = pjwg + (s * O + o) * R;
            #pragma unroll
            for (int r = 0; r < R; ++r) {
                a1 = fmaf(w4r[r], qas[r * V * V + uv], a1);
                a2 = fmaf(pjr[r], ta[r * V * V + uv], a2);
            }
            val = fmaf(alpha, a1, Ag[s * V * V + uv]) + beta * a2;
        }
        dst[idx] = val;
    }
}

// ---------------- K3: fused x3-GEMM + R-apply ----------------
constexpr int XS0 = 0;                        // 26624 floats
constexpr int WS0 = 26624;                    // 4096
constexpr int B30 = 30720;                    // 64
constexpr int RS0 = 30784;                    // 22400
constexpr int K3_SMEM_F = 53184;
constexpr int K3_SMEM_B = K3_SMEM_F * 4;      // 212736 bytes

template <int NP>
__device__ __forceinline__ void contract_half(ull* __restrict__ x3p,
                                              const float* __restrict__ Rb,
                                              float* __restrict__ zt0,
                                              float* __restrict__ zt1)
{
    // in-place transpose: t-packed pairs -> v-packed per t (no extra arrays)
    #pragma unroll
    for (int j = 0; j < NP; ++j) {
        float p0, p1, q0, q1;
        upk(p0, p1, x3p[2 * j]);
        upk(q0, q1, x3p[2 * j + 1]);
        x3p[2 * j]     = pk(p0, q0);   // t0: (v_even, v_odd)
        x3p[2 * j + 1] = pk(p1, q1);   // t1: (v_even, v_odd)
    }
    #pragma unroll
    for (int u = 0; u < 25; ++u) {
        const ull* Rp = reinterpret_cast<const ull*>(Rb + u * 14);
        ull acc0 = 0ull, acc1 = 0ull;
        #pragma unroll
        for (int j = 0; j < NP; ++j) {
            ull r = Rp[j];
            acc0 = f2fma(x3p[2 * j],     r, acc0);
            acc1 = f2fma(x3p[2 * j + 1], r, acc1);
        }
        float e0, e1, f0, f1;
        upk(e0, e1, acc0);
        upk(f0, f1, acc1);
        zt0[u] += e0 + e1;
        zt1[u] += f0 + f1;
    }
}

__global__ void __launch_bounds__(512, 1) k_main(const float* __restrict__ x,
                                                 const float* __restrict__ b3g,
                                                 float* __restrict__ ybuf)
{
    extern __shared__ float sm[];
    int n = blockIdx.y, tb = blockIdx.x * TT;
    int tid = threadIdx.x, wid = tid >> 5, lane = tid & 31;
    int tp  = wid & 7;          // t-pair: t0 = tp, t1 = tp + 8
    int och = wid >> 3;         // o-chunk

    // ---- fill packed x tile ----
    for (int idx = tid; idx < C * TT * 13; idx += 512) {
        int k = idx % 13;
        int t = (idx / 13) % TT;
        int c = idx / (13 * TT);
        const float* src = x + (((size_t)(n * C + c)) * T + tb + t) * V;
        float a = src[2 * k];
        float b = (k < 12) ? src[2 * k + 1] : 0.f;
        int w  = t & 7;
        int hi = t >> 3;
        float* dst = sm + XS0 + ((c * 13 + k) * 8 + w) * 4;
        dst[hi]     = a;
        dst[2 + hi] = b;
    }

    float z[2][25];
    #pragma unroll
    for (int b = 0; b < 2; ++b)
        #pragma unroll
        for (int u = 0; u < 25; ++u) z[b][u] = 0.f;

    int o = och * 32 + lane;

    #pragma unroll 1
    for (int s = 0; s < S; ++s) {
        __syncthreads();
        // w3t + b3 + R half A (all coalesced float4 streams)
        {
            const float4* Wg = reinterpret_cast<const float4*>(g_w3t + s * C * O);
            float4* Wd = reinterpret_cast<float4*>(sm + WS0);
            for (int idx = tid; idx < 1024; idx += 512) Wd[idx] = Wg[idx];
        }
        if (tid < O) sm[B30 + tid] = b3g[s * O + tid];
        {
            const float4* Rg = reinterpret_cast<const float4*>(
                g_R2 + ((size_t)(s * NB + n)) * 2 * 22400);
            float4* Rd = reinterpret_cast<float4*>(sm + RS0);
            for (int idx = tid; idx < 5600; idx += 512) Rd[idx] = Rg[idx];
        }
        __syncthreads();

        float bbs = sm[B30 + o];
        ull  bl   = pk(bbs, bbs);

        // ---- phase A: x3 for v=0..13 ----
        {
            ull x3p[14];
            #pragma unroll
            for (int v = 0; v < 14; ++v) x3p[v] = bl;
            #pragma unroll 2
            for (int c = 0; c < C; ++c) {
                float wv = sm[WS0 + (c << 6) + o];
                ull wl = pk(wv, wv);
                const float* xb = sm + XS0 + (c * 13) * 32 + tp * 4;
                #pragma unroll
                for (int k = 0; k < 7; ++k) {
                    ulonglong2 qq = *reinterpret_cast<const ulonglong2*>(xb + k * 32);
                    x3p[2 * k]     = f2fma(qq.x, wl, x3p[2 * k]);
                    x3p[2 * k + 1] = f2fma(qq.y, wl, x3p[2 * k + 1]);
                }
            }
            contract_half<7>(x3p, sm + RS0 + (size_t)o * 350, z[0], z[1]);
        }

        __syncthreads();
        // R half B
        {
            const float4* Rg = reinterpret_cast<const float4*>(
                g_R2 + ((size_t)(s * NB + n)) * 2 * 22400 + 22400);
            float4* Rd = reinterpret_cast<float4*>(sm + RS0);
            for (int idx = tid; idx < 5600; idx += 512) Rd[idx] = Rg[idx];
        }
        __syncthreads();

        // ---- phase B: x3 for v=14..24 ----
        {
            ull x3p[12];
            #pragma unroll
            for (int v = 0; v < 12; ++v) x3p[v] = bl;
            #pragma unroll 2
            for (int c = 0; c < C; ++c) {
                float wv = sm[WS0 + (c << 6) + o];
                ull wl = pk(wv, wv);
                const float* xb = sm + XS0 + (c * 13) * 32 + tp * 4;
                #pragma unroll
                for (int k = 7; k < 13; ++k) {
                    ulonglong2 qq = *reinterpret_cast<const ulonglong2*>(xb + k * 32);
                    int b2 = k - 7;
                    x3p[2 * b2]     = f2fma(qq.x, wl, x3p[2 * b2]);
                    x3p[2 * b2 + 1] = f2fma(qq.y, wl, x3p[2 * b2 + 1]);
                }
            }
            contract_half<6>(x3p, sm + RS0 + (size_t)o * 350, z[0], z[1]);
        }
    }

    // ---- stage + coalesced store ----
    __syncthreads();
    #pragma unroll
    for (int u = 0; u < 25; ++u) {
        sm[o * 401 + tp * 25 + u]       = z[0][u];
        sm[o * 401 + (tp + 8) * 25 + u] = z[1][u];
    }
    __syncthreads();
    for (int idx = tid; idx < O * TT * V; idx += 512) {
        int oo = idx / (TT * V), tu = idx % (TT * V);
        ybuf[((size_t)(n * O + oo) * T + tb) * V + tu] = sm[oo * 401 + tu];
    }
}

// ---------------- K4a/K4b: BN stats ----------------
__global__ void k_stats1(const float* __restrict__ ybuf)
{
    __shared__ float rs[256], rq[256];
    int o = blockIdx.x, chunk = blockIdx.y;
    int tid = threadIdx.x;
    float s = 0.f, s2 = 0.f;
    for (int nn = 0; nn < 4; ++nn) {
        const float* base = ybuf + ((size_t)((chunk * 4 + nn) * O + o)) * (T * V);
        for (int i = tid; i < T * V; i += 256) {
            float v = base[i];
            s += v; s2 = fmaf(v, v, s2);
        }
    }
    rs[tid] = s; rq[tid] = s2;
    __syncthreads();
    for (int st = 128; st > 0; st >>= 1) {
        if (tid < st) { rs[tid] += rs[tid + st]; rq[tid] += rq[tid + st]; }
        __syncthreads();
    }
    if (tid == 0) g_part[o * 16 + chunk] = make_float2(rs[0], rq[0]);
}

__global__ void k_stats2(const float* __restrict__ bnw, const float* __restrict__ bnb)
{
    int o = threadIdx.x;
    float s = 0.f, s2 = 0.f;
    for (int c = 0; c < 16; ++c) { float2 p = g_part[o * 16 + c]; s += p.x; s2 += p.y; }
    float M = (float)(NB * T * V);
    float mean = s / M;
    float var  = s2 / M - mean * mean;
    float sc = bnw[o] * rsqrtf(var + 1e-5f);
    g_stats[o] = make_float2(sc, bnb[o] - mean * sc);
}

// ---------------- K5: BN apply + residual + relu ----------------
__global__ void k_final(float4* __restrict__ ybuf, const float4* __restrict__ x)
{
    int idx = blockIdx.x * 256 + threadIdx.x;
    int o = (idx / (T * V / 4)) & 63;
    float2 ss = g_stats[o];
    float4 y = ybuf[idx], xx = x[idx];
    y.x = fmaxf(fmaf(y.x, ss.x, ss.y) + xx.x, 0.f);
    y.y = fmaxf(fmaf(y.y, ss.x, ss.y) + xx.y, 0.f);
    y.z = fmaxf(fmaf(y.z, ss.x, ss.y) + xx.z, 0.f);
    y.w = fmaxf(fmaf(y.w, ss.x, ss.y) + xx.w, 0.f);
    ybuf[idx] = y;
}

// ---------------- launch ----------------
extern "C" void kernel_launch(void* const* d_in, const int* in_sizes, int n_in,
                              void* d_out, int out_size)
{
    (void)in_sizes; (void)n_in; (void)out_size;
    const float* x    = (const float*)d_in[0];
    const float* A    = (const float*)d_in[1];
    const float* alph = (const float*)d_in[2];
    const float* w1   = (const float*)d_in[3];
    const float* b1   = (const float*)d_in[4];
    const float* w2   = (const float*)d_in[5];
    const float* b2   = (const float*)d_in[6];
    const float* w3   = (const float*)d_in[7];
    const float* b3   = (const float*)d_in[8];
    const float* w4   = (const float*)d_in[9];
    const float* b4   = (const float*)d_in[10];
    const float* pw1  = (const float*)d_in[11];
    const float* pb1  = (const float*)d_in[12];
    const float* pw2  = (const float*)d_in[13];
    const float* pb2  = (const float*)d_in[14];
    const float* dww  = (const float*)d_in[15];
    const float* pjw  = (const float*)d_in[16];
    const float* beta = (const float*)d_in[17];
    const float* gamma= (const float*)d_in[18];
    const float* bnw  = (const float*)d_in[19];
    const float* bnb  = (const float*)d_in[20];
    float* out = (float*)d_out;

    cudaFuncSetAttribute(k_main, cudaFuncAttributeMaxDynamicSharedMemorySize, K3_SMEM_B);
    cudaFuncSetAttribute(k_R,    cudaFuncAttributeMaxDynamicSharedMemorySize, 15800 * 4);

    k_xm<<<NB * C, 256>>>(x);
    k_w3t<<<S * C * O / 256, 256>>>(w3);
    k_R<<<dim3(NB, S), 256, 15800 * 4>>>(A, alph, w1, b1, w2, b2, w4, b4,
                                         pw1, pb1, pw2, pb2, dww, pjw, beta, gamma);
    k_main<<<dim3(T / TT, NB), 512, K3_SMEM_B>>>(x, b3, out);
    k_stats1<<<dim3(O, 16), 256>>>(out);
    k_stats2<<<1, O>>>(bnw, bnb);
    k_final<<<(NB * C * T * V) / 1024, 256>>>((float4*)out, (const float4*)x);
}

// round 5
// speedup vs baseline: 1.3992x; 1.0058x over previous
#include <cuda_runtime.h>

#define NB 64
#define C  64
#define T  256
#define V  25
#define S  3
#define R  8
#define O  64
#define TT 16

typedef unsigned long long ull;

// ---------------- scratch ----------------
__device__ float  g_xm[NB * C * V];
__device__ float  g_R2[S * NB * 2 * 22400];      // padded/split R: [s][n][h][o*350+u*14+j]
__device__ float  g_w3t[S * C * O];              // w3 transposed: [s][c][o]
__device__ float2 g_stats[O];
__device__ float2 g_part[O * 16];

// ---------------- f32x2 helpers ----------------
__device__ __forceinline__ ull pk(float lo, float hi) {
    ull r; asm("mov.b64 %0, {%1,%2};" : "=l"(r) : "f"(lo), "f"(hi)); return r;
}
__device__ __forceinline__ void upk(float& lo, float& hi, ull v) {
    asm("mov.b64 {%0,%1}, %2;" : "=f"(lo), "=f"(hi) : "l"(v));
}
__device__ __forceinline__ ull f2fma(ull a, ull b, ull c) {
    ull d; asm("fma.rn.f32x2 %0, %1, %2, %3;" : "=l"(d) : "l"(a), "l"(b), "l"(c)); return d;
}

// ---------------- K1: xm[n,c,v] = mean_t x ----------------
__global__ void k_xm(const float* __restrict__ x) {
    __shared__ float red[256 * V];
    int bx  = blockIdx.x;
    int tid = threadIdx.x;
    const float* row = x + (size_t)bx * T * V + (size_t)tid * V;
    #pragma unroll
    for (int v = 0; v < V; ++v) red[tid * V + v] = row[v];
    __syncthreads();
    for (int st = 128; st > 0; st >>= 1) {
        if (tid < st) {
            #pragma unroll
            for (int v = 0; v < V; ++v) red[tid * V + v] += red[(tid + st) * V + v];
        }
        __syncthreads();
    }
    if (tid < V) g_xm[bx * V + tid] = red[tid] * (1.0f / T);
}

// ---------------- K1b: transpose w3 -> [s][c][o] ----------------
__global__ void k_w3t(const float* __restrict__ w3g) {
    int idx = blockIdx.x * 256 + threadIdx.x;     // s*4096 + c*64 + o
    int s = idx >> 12, co = idx & 4095, c = co >> 6, o = co & 63;
    g_w3t[idx] = w3g[(s * O + o) * C + c];
}

// ---------------- K2: build padded/split R2 ----------------
__global__ void k_R(const float* __restrict__ Ag,   const float* __restrict__ alphag,
                    const float* __restrict__ w1g,  const float* __restrict__ b1g,
                    const float* __restrict__ w2g,  const float* __restrict__ b2g,
                    const float* __restrict__ w4g,  const float* __restrict__ b4g,
                    const float* __restrict__ pw1g, const float* __restrict__ pb1g,
                    const float* __restrict__ pw2g, const float* __restrict__ pb2g,
                    const float* __restrict__ dwwg, const float* __restrict__ pjwg,
                    const float* __restrict__ betag,const float* __restrict__ gammag)
{
    extern __shared__ float sm[];
    float* q1s = sm;            // 5000 (reused as ta)
    float* qas = sm + 5000;     // 5000
    float* ds  = sm + 10000;    // 5000
    float* x1s = sm + 15000;    // 200
    float* x2s = sm + 15200;    // 200
    float* as_ = sm + 15400;    // 200
    float* bs_ = sm + 15600;    // 200

    int n = blockIdx.x, s = blockIdx.y;
    int tid = threadIdx.x;
    const float* xm = g_xm + n * (C * V);

    for (int idx = tid; idx < R * V; idx += blockDim.x) {
        int r = idx / V, u = idx % V;
        float s1 = b1g[s * R + r], s2 = b2g[s * R + r];
        const float* w1r = w1g + (s * R + r) * C;
        const float* w2r = w2g + (s * R + r) * C;
        for (int c = 0; c < C; ++c) {
            float xv = xm[c * V + u];
            s1 = fmaf(w1r[c], xv, s1);
            s2 = fmaf(w2r[c], xv, s2);
        }
        x1s[idx] = s1; x2s[idx] = s2;
    }
    __syncthreads();
    for (int idx = tid; idx < R * V; idx += blockDim.x) {
        int r = idx / V, u = idx % V;
        const float* p1 = pw1g + (s * R + r) * (2 * R);
        float av = 0.f, bv = 0.f;
        #pragma unroll
        for (int p = 0; p < R; ++p) {
            av = fmaf(p1[p],     x2s[p * V + u], av);
            bv = fmaf(p1[R + p], x2s[p * V + u], bv);
        }
        as_[idx] = av; bs_[idx] = bv;
    }
    __syncthreads();
    for (int idx = tid; idx < R * V * V; idx += blockDim.x) {
        int r = idx / (V * V), uv = idx % (V * V), u = uv / V, v = uv % V;
        q1s[idx] = tanhf(x1s[r * V + u] - x2s[r * V + v]);
    }
    __syncthreads();
    float gma = gammag[s];
    for (int uv = tid; uv < V * V; uv += blockDim.x) {
        int u = uv / V, v = uv % V;
        float h[R];
        #pragma unroll
        for (int p = 0; p < R; ++p)
            h[p] = fmaxf(as_[p * V + u] + bs_[p * V + v] + pb1g[s * R + p], 0.f);
        #pragma unroll
        for (int r = 0; r < R; ++r) {
            float q2 = pb2g[s * R + r];
            const float* p2 = pw2g + (s * R + r) * R;
            #pragma unroll
            for (int p = 0; p < R; ++p) q2 = fmaf(p2[p], h[p], q2);
            qas[r * V * V + uv] = q1s[r * V * V + uv] + gma * q2;
        }
    }
    __syncthreads();
    for (int idx = tid; idx < R * V * V; idx += blockDim.x) {
        int r = idx / (V * V), uv = idx % (V * V), u = uv / V, v = uv % V;
        const float* kw = dwwg + (s * R + r) * 9;
        float acc = 0.f;
        #pragma unroll
        for (int ki = 0; ki < 3; ++ki) {
            int uu = u + ki - 1; if (uu < 0 || uu >= V) continue;
            #pragma unroll
            for (int kj = 0; kj < 3; ++kj) {
                int vv = v + kj - 1; if (vv < 0 || vv >= V) continue;
                acc = fmaf(q1s[r * V * V + uu * V + vv], kw[ki * 3 + kj], acc);
            }
        }
        ds[idx] = acc;
    }
    __syncthreads();
    for (int idx = tid; idx < R * V * V; idx += blockDim.x) {
        int r = idx / (V * V), uv = idx % (V * V), u = uv / V, v = uv % V;
        float acc = 0.f;
        for (int ki = -1; ki <= 1; ++ki) {
            int uu = u + ki; if (uu < 0 || uu >= V) continue;
            for (int kj = -1; kj <= 1; ++kj) {
                int vv = v + kj; if (vv < 0 || vv >= V) continue;
                acc += ds[r * V * V + uu * V + vv];
            }
        }
        q1s[idx] = tanhf(acc * (1.f / 9.f));
    }
    __syncthreads();
    float alpha = alphag[0], beta = betag[s];
    const float* ta = q1s;
    float* dst = g_R2 + ((size_t)(s * NB + n)) * 2 * 22400;
    for (int idx = tid; idx < 2 * 22400; idx += blockDim.x) {
        int h   = idx / 22400;
        int rem = idx % 22400;
        int o   = rem / 350;
        int uj  = rem % 350;
        int u   = uj / 14, j = uj % 14;
        int v   = h * 14 + j;
        float val = 0.f;
        if (v < V) {
            int uv = u * V + v;
            float a1 = b4g[s * O + o], a2 = 0.f;
            const float* w4r = w4g + (s * O + o) * R;
            const float* pjr = pjwg + (s * O + o) * R;
            #pragma unroll
            for (int r = 0; r < R; ++r) {
                a1 = fmaf(w4r[r], qas[r * V * V + uv], a1);
                a2 = fmaf(pjr[r], ta[r * V * V + uv], a2);
            }
            val = fmaf(alpha, a1, Ag[s * V * V + uv]) + beta * a2;
        }
        dst[idx] = val;
    }
}

// ---------------- K3: fused x3-GEMM + R-apply ----------------
constexpr int XS0 = 0;                        // 26624 floats
constexpr int WS0 = 26624;                    // 4096
constexpr int B30 = 30720;                    // 64
constexpr int RS0 = 30784;                    // 22400
constexpr int K3_SMEM_F = 53184;
constexpr int K3_SMEM_B = K3_SMEM_F * 4;      // 212736 bytes

template <int NP>
__device__ __forceinline__ void contract_half(ull* __restrict__ x3p,
                                              const float* __restrict__ Rb,
                                              float* __restrict__ zt0,
                                              float* __restrict__ zt1)
{
    // in-place transpose: t-packed pairs -> v-packed per t (no extra arrays)
    #pragma unroll
    for (int j = 0; j < NP; ++j) {
        float p0, p1, q0, q1;
        upk(p0, p1, x3p[2 * j]);
        upk(q0, q1, x3p[2 * j + 1]);
        x3p[2 * j]     = pk(p0, q0);   // t0: (v_even, v_odd)
        x3p[2 * j + 1] = pk(p1, q1);   // t1: (v_even, v_odd)
    }
    #pragma unroll
    for (int u = 0; u < 25; ++u) {
        const ull* Rp = reinterpret_cast<const ull*>(Rb + u * 14);
        ull acc0 = 0ull, acc1 = 0ull;
        #pragma unroll
        for (int j = 0; j < NP; ++j) {
            ull r = Rp[j];
            acc0 = f2fma(x3p[2 * j],     r, acc0);
            acc1 = f2fma(x3p[2 * j + 1], r, acc1);
        }
        float e0, e1, f0, f1;
        upk(e0, e1, acc0);
        upk(f0, f1, acc1);
        zt0[u] += e0 + e1;
        zt1[u] += f0 + f1;
    }
}

__global__ void __launch_bounds__(512, 1) k_main(const float* __restrict__ x,
                                                 const float* __restrict__ b3g,
                                                 float* __restrict__ ybuf)
{
    extern __shared__ float sm[];
    int n = blockIdx.y, tb = blockIdx.x * TT;
    int tid = threadIdx.x, wid = tid >> 5, lane = tid & 31;
    int tp  = wid & 7;          // t-pair: t0 = tp, t1 = tp + 8
    int och = wid >> 3;         // o-chunk

    // ---- fill packed x tile ----
    for (int idx = tid; idx < C * TT * 13; idx += 512) {
        int k = idx % 13;
        int t = (idx / 13) % TT;
        int c = idx / (13 * TT);
        const float* src = x + (((size_t)(n * C + c)) * T + tb + t) * V;
        float a = src[2 * k];
        float b = (k < 12) ? src[2 * k + 1] : 0.f;
        int w  = t & 7;
        int hi = t >> 3;
        float* dst = sm + XS0 + ((c * 13 + k) * 8 + w) * 4;
        dst[hi]     = a;
        dst[2 + hi] = b;
    }

    float z[2][25];
    #pragma unroll
    for (int b = 0; b < 2; ++b)
        #pragma unroll
        for (int u = 0; u < 25; ++u) z[b][u] = 0.f;

    int o = och * 32 + lane;

    #pragma unroll 1
    for (int s = 0; s < S; ++s) {
        __syncthreads();
        // w3t + b3 + R half A (all coalesced float4 streams)
        {
            const float4* Wg = reinterpret_cast<const float4*>(g_w3t + s * C * O);
            float4* Wd = reinterpret_cast<float4*>(sm + WS0);
            for (int idx = tid; idx < 1024; idx += 512) Wd[idx] = Wg[idx];
        }
        if (tid < O) sm[B30 + tid] = b3g[s * O + tid];
        {
            const float4* Rg = reinterpret_cast<const float4*>(
                g_R2 + ((size_t)(s * NB + n)) * 2 * 22400);
            float4* Rd = reinterpret_cast<float4*>(sm + RS0);
            for (int idx = tid; idx < 5600; idx += 512) Rd[idx] = Rg[idx];
        }
        __syncthreads();

        float bbs = sm[B30 + o];
        ull  bl   = pk(bbs, bbs);

        // ---- phase A: x3 for v=0..13 ----
        {
            ull x3p[14];
            #pragma unroll
            for (int v = 0; v < 14; ++v) x3p[v] = bl;
            #pragma unroll 2
            for (int c = 0; c < C; ++c) {
                float wv = sm[WS0 + (c << 6) + o];
                ull wl = pk(wv, wv);
                const float* xb = sm + XS0 + (c * 13) * 32 + tp * 4;
                #pragma unroll
                for (int k = 0; k < 7; ++k) {
                    ulonglong2 qq = *reinterpret_cast<const ulonglong2*>(xb + k * 32);
                    x3p[2 * k]     = f2fma(qq.x, wl, x3p[2 * k]);
                    x3p[2 * k + 1] = f2fma(qq.y, wl, x3p[2 * k + 1]);
                }
            }
            contract_half<7>(x3p, sm + RS0 + (size_t)o * 350, z[0], z[1]);
        }

        __syncthreads();
        // R half B
        {
            const float4* Rg = reinterpret_cast<const float4*>(
                g_R2 + ((size_t)(s * NB + n)) * 2 * 22400 + 22400);
            float4* Rd = reinterpret_cast<float4*>(sm + RS0);
            for (int idx = tid; idx < 5600; idx += 512) Rd[idx] = Rg[idx];
        }
        __syncthreads();

        // ---- phase B: x3 for v=14..24 ----
        {
            ull x3p[12];
            #pragma unroll
            for (int v = 0; v < 12; ++v) x3p[v] = bl;
            #pragma unroll 2
            for (int c = 0; c < C; ++c) {
                float wv = sm[WS0 + (c << 6) + o];
                ull wl = pk(wv, wv);
                const float* xb = sm + XS0 + (c * 13) * 32 + tp * 4;
                #pragma unroll
                for (int k = 7; k < 13; ++k) {
                    ulonglong2 qq = *reinterpret_cast<const ulonglong2*>(xb + k * 32);
                    int b2 = k - 7;
                    x3p[2 * b2]     = f2fma(qq.x, wl, x3p[2 * b2]);
                    x3p[2 * b2 + 1] = f2fma(qq.y, wl, x3p[2 * b2 + 1]);
                }
            }
            contract_half<6>(x3p, sm + RS0 + (size_t)o * 350, z[0], z[1]);
        }
    }

    // ---- stage + coalesced store ----
    __syncthreads();
    #pragma unroll
    for (int u = 0; u < 25; ++u) {
        sm[o * 401 + tp * 25 + u]       = z[0][u];
        sm[o * 401 + (tp + 8) * 25 + u] = z[1][u];
    }
    __syncthreads();
    for (int idx = tid; idx < O * TT * V; idx += 512) {
        int oo = idx / (TT * V), tu = idx % (TT * V);
        ybuf[((size_t)(n * O + oo) * T + tb) * V + tu] = sm[oo * 401 + tu];
    }
}

// ---------------- K4a/K4b: BN stats ----------------
__global__ void k_stats1(const float* __restrict__ ybuf)
{
    __shared__ float rs[256], rq[256];
    int o = blockIdx.x, chunk = blockIdx.y;
    int tid = threadIdx.x;
    float s = 0.f, s2 = 0.f;
    for (int nn = 0; nn < 4; ++nn) {
        const float* base = ybuf + ((size_t)((chunk * 4 + nn) * O + o)) * (T * V);
        for (int i = tid; i < T * V; i += 256) {
            float v = base[i];
            s += v; s2 = fmaf(v, v, s2);
        }
    }
    rs[tid] = s; rq[tid] = s2;
    __syncthreads();
    for (int st = 128; st > 0; st >>= 1) {
        if (tid < st) { rs[tid] += rs[tid + st]; rq[tid] += rq[tid + st]; }
        __syncthreads();
    }
    if (tid == 0) g_part[o * 16 + chunk] = make_float2(rs[0], rq[0]);
}

__global__ void k_stats2(const float* __restrict__ bnw, const float* __restrict__ bnb)
{
    int o = threadIdx.x;
    float s = 0.f, s2 = 0.f;
    for (int c = 0; c < 16; ++c) { float2 p = g_part[o * 16 + c]; s += p.x; s2 += p.y; }
    float M = (float)(NB * T * V);
    float mean = s / M;
    float var  = s2 / M - mean * mean;
    float sc = bnw[o] * rsqrtf(var + 1e-5f);
    g_stats[o] = make_float2(sc, bnb[o] - mean * sc);
}

// ---------------- K5: BN apply + residual + relu ----------------
__global__ void k_final(float4* __restrict__ ybuf, const float4* __restrict__ x)
{
    int idx = blockIdx.x * 256 + threadIdx.x;
    int o = (idx / (T * V / 4)) & 63;
    float2 ss = g_stats[o];
    float4 y = ybuf[idx], xx = x[idx];
    y.x = fmaxf(fmaf(y.x, ss.x, ss.y) + xx.x, 0.f);
    y.y = fmaxf(fmaf(y.y, ss.x, ss.y) + xx.y, 0.f);
    y.z = fmaxf(fmaf(y.z, ss.x, ss.y) + xx.z, 0.f);
    y.w = fmaxf(fmaf(y.w, ss.x, ss.y) + xx.w, 0.f);
    ybuf[idx] = y;
}

// ---------------- launch ----------------
extern "C" void kernel_launch(void* const* d_in, const int* in_sizes, int n_in,
                              void* d_out, int out_size)
{
    (void)in_sizes; (void)n_in; (void)out_size;
    const float* x    = (const float*)d_in[0];
    const float* A    = (const float*)d_in[1];
    const float* alph = (const float*)d_in[2];
    const float* w1   = (const float*)d_in[3];
    const float* b1   = (const float*)d_in[4];
    const float* w2   = (const float*)d_in[5];
    const float* b2   = (const float*)d_in[6];
    const float* w3   = (const float*)d_in[7];
    const float* b3   = (const float*)d_in[8];
    const float* w4   = (const float*)d_in[9];
    const float* b4   = (const float*)d_in[10];
    const float* pw1  = (const float*)d_in[11];
    const float* pb1  = (const float*)d_in[12];
    const float* pw2  = (const float*)d_in[13];
    const float* pb2  = (const float*)d_in[14];
    const float* dww  = (const float*)d_in[15];
    const float* pjw  = (const float*)d_in[16];
    const float* beta = (const float*)d_in[17];
    const float* gamma= (const float*)d_in[18];
    const float* bnw  = (const float*)d_in[19];
    const float* bnb  = (const float*)d_in[20];
    float* out = (float*)d_out;

    cudaFuncSetAttribute(k_main, cudaFuncAttributeMaxDynamicSharedMemorySize, K3_SMEM_B);
    cudaFuncSetAttribute(k_R,    cudaFuncAttributeMaxDynamicSharedMemorySize, 15800 * 4);

    k_xm<<<NB * C, 256>>>(x);
    k_w3t<<<S * C * O / 256, 256>>>(w3);
    k_R<<<dim3(NB, S), 256, 15800 * 4>>>(A, alph, w1, b1, w2, b2, w4, b4,
                                         pw1, pb1, pw2, pb2, dww, pjw, beta, gamma);
    k_main<<<dim3(T / TT, NB), 512, K3_SMEM_B>>>(x, b3, out);
    k_stats1<<<dim3(O, 16), 256>>>(out);
    k_stats2<<<1, O>>>(bnw, bnb);
    k_final<<<(NB * C * T * V) / 1024, 256>>>((float4*)out, (const float4*)x);
}

// round 6
// speedup vs baseline: 1.8178x; 1.2992x over previous
#include <cuda_runtime.h>

#define NB 64
#define C  64
#define T  256
#define V  25
#define S  3
#define R  8
#define O  64

typedef unsigned long long ull;

// ---------------- scratch ----------------
__device__ float  g_xm[NB * C * V];
__device__ ull    g_w3p[S * C * 32];             // pk(w3[s][2op][c], w3[s][2op+1][c]), [s][c][op]
__device__ ull    g_R3[(size_t)S * NB * O * 13 * 25];   // pk(R[2k][v], R[2k+1][v])
__device__ float  g_x3[(size_t)S * NB * O * T * V];     // x3[s][n][o][t*25+v]
__device__ float2 g_stats[O];
__device__ float2 g_part[O * 16];

// ---------------- f32x2 helpers ----------------
__device__ __forceinline__ ull pk(float lo, float hi) {
    ull r; asm("mov.b64 %0, {%1,%2};" : "=l"(r) : "f"(lo), "f"(hi)); return r;
}
__device__ __forceinline__ void upk(float& lo, float& hi, ull v) {
    asm("mov.b64 {%0,%1}, %2;" : "=f"(lo), "=f"(hi) : "l"(v));
}
__device__ __forceinline__ ull f2fma(ull a, ull b, ull c) {
    ull d; asm("fma.rn.f32x2 %0, %1, %2, %3;" : "=l"(d) : "l"(a), "l"(b), "l"(c)); return d;
}

// ---------------- K1: xm[n,c,v] = mean_t x ----------------
__global__ void k_xm(const float* __restrict__ x) {
    __shared__ float red[256 * V];
    int bx  = blockIdx.x;
    int tid = threadIdx.x;
    const float* row = x + (size_t)bx * T * V + (size_t)tid * V;
    #pragma unroll
    for (int v = 0; v < V; ++v) red[tid * V + v] = row[v];
    __syncthreads();
    for (int st = 128; st > 0; st >>= 1) {
        if (tid < st) {
            #pragma unroll
            for (int v = 0; v < V; ++v) red[tid * V + v] += red[(tid + st) * V + v];
        }
        __syncthreads();
    }
    if (tid < V) g_xm[bx * V + tid] = red[tid] * (1.0f / T);
}

// ---------------- K1b: pack w3 into o-pair f32x2, layout [s][c][op] ----------------
__global__ void k_w3p(const float* __restrict__ w3g) {
    int idx = blockIdx.x * 256 + threadIdx.x;        // < S*C*32
    int s = idx / (C * 32), rem = idx % (C * 32), c = rem >> 5, op = rem & 31;
    g_w3p[idx] = pk(w3g[(s * O + 2 * op) * C + c], w3g[(s * O + 2 * op + 1) * C + c]);
}

// ---------------- K2: build R3 (u-pair packed) ----------------
__global__ void k_R(const float* __restrict__ Ag,   const float* __restrict__ alphag,
                    const float* __restrict__ w1g,  const float* __restrict__ b1g,
                    const float* __restrict__ w2g,  const float* __restrict__ b2g,
                    const float* __restrict__ w4g,  const float* __restrict__ b4g,
                    const float* __restrict__ pw1g, const float* __restrict__ pb1g,
                    const float* __restrict__ pw2g, const float* __restrict__ pb2g,
                    const float* __restrict__ dwwg, const float* __restrict__ pjwg,
                    const float* __restrict__ betag,const float* __restrict__ gammag)
{
    extern __shared__ float sm[];
    float* q1s = sm;            // 5000 (reused as ta)
    float* qas = sm + 5000;     // 5000
    float* ds  = sm + 10000;    // 5000
    float* x1s = sm + 15000;    // 200
    float* x2s = sm + 15200;    // 200
    float* as_ = sm + 15400;    // 200
    float* bs_ = sm + 15600;    // 200

    int n = blockIdx.x, s = blockIdx.y;
    int tid = threadIdx.x;
    const float* xm = g_xm + n * (C * V);

    for (int idx = tid; idx < R * V; idx += blockDim.x) {
        int r = idx / V, u = idx % V;
        float s1 = b1g[s * R + r], s2 = b2g[s * R + r];
        const float* w1r = w1g + (s * R + r) * C;
        const float* w2r = w2g + (s * R + r) * C;
        for (int c = 0; c < C; ++c) {
            float xv = xm[c * V + u];
            s1 = fmaf(w1r[c], xv, s1);
            s2 = fmaf(w2r[c], xv, s2);
        }
        x1s[idx] = s1; x2s[idx] = s2;
    }
    __syncthreads();
    for (int idx = tid; idx < R * V; idx += blockDim.x) {
        int r = idx / V, u = idx % V;
        const float* p1 = pw1g + (s * R + r) * (2 * R);
        float av = 0.f, bv = 0.f;
        #pragma unroll
        for (int p = 0; p < R; ++p) {
            av = fmaf(p1[p],     x2s[p * V + u], av);
            bv = fmaf(p1[R + p], x2s[p * V + u], bv);
        }
        as_[idx] = av; bs_[idx] = bv;
    }
    __syncthreads();
    for (int idx = tid; idx < R * V * V; idx += blockDim.x) {
        int r = idx / (V * V), uv = idx % (V * V), u = uv / V, v = uv % V;
        q1s[idx] = tanhf(x1s[r * V + u] - x2s[r * V + v]);
    }
    __syncthreads();
    float gma = gammag[s];
    for (int uv = tid; uv < V * V; uv += blockDim.x) {
        int u = uv / V, v = uv % V;
        float h[R];
        #pragma unroll
        for (int p = 0; p < R; ++p)
            h[p] = fmaxf(as_[p * V + u] + bs_[p * V + v] + pb1g[s * R + p], 0.f);
        #pragma unroll
        for (int r = 0; r < R; ++r) {
            float q2 = pb2g[s * R + r];
            const float* p2 = pw2g + (s * R + r) * R;
            #pragma unroll
            for (int p = 0; p < R; ++p) q2 = fmaf(p2[p], h[p], q2);
            qas[r * V * V + uv] = q1s[r * V * V + uv] + gma * q2;
        }
    }
    __syncthreads();
    for (int idx = tid; idx < R * V * V; idx += blockDim.x) {
        int r = idx / (V * V), uv = idx % (V * V), u = uv / V, v = uv % V;
        const float* kw = dwwg + (s * R + r) * 9;
        float acc = 0.f;
        #pragma unroll
        for (int ki = 0; ki < 3; ++ki) {
            int uu = u + ki - 1; if (uu < 0 || uu >= V) continue;
            #pragma unroll
            for (int kj = 0; kj < 3; ++kj) {
                int vv = v + kj - 1; if (vv < 0 || vv >= V) continue;
                acc = fmaf(q1s[r * V * V + uu * V + vv], kw[ki * 3 + kj], acc);
            }
        }
        ds[idx] = acc;
    }
    __syncthreads();
    for (int idx = tid; idx < R * V * V; idx += blockDim.x) {
        int r = idx / (V * V), uv = idx % (V * V), u = uv / V, v = uv % V;
        float acc = 0.f;
        for (int ki = -1; ki <= 1; ++ki) {
            int uu = u + ki; if (uu < 0 || uu >= V) continue;
            for (int kj = -1; kj <= 1; ++kj) {
                int vv = v + kj; if (vv < 0 || vv >= V) continue;
                acc += ds[r * V * V + uu * V + vv];
            }
        }
        q1s[idx] = tanhf(acc * (1.f / 9.f));
    }
    __syncthreads();
    // g_R3[s][n][o][k][v] = pk(Rfull[2k][v], Rfull[2k+1][v])
    float alpha = alphag[0], beta = betag[s];
    const float* ta = q1s;
    ull* dst = g_R3 + ((size_t)(s * NB + n)) * O * 325;
    for (int idx = tid; idx < O * 325; idx += blockDim.x) {
        int o = idx / 325, kv = idx % 325, k = kv / 25, v = kv % 25;
        const float* w4r = w4g + (s * O + o) * R;
        const float* pjr = pjwg + (s * O + o) * R;
        float vals[2];
        #pragma unroll
        for (int h2 = 0; h2 < 2; ++h2) {
            int u = 2 * k + h2;
            float val = 0.f;
            if (u < V) {
                int uv = u * V + v;
                float a1 = b4g[s * O + o], a2 = 0.f;
                #pragma unroll
                for (int r = 0; r < R; ++r) {
                    a1 = fmaf(w4r[r], qas[r * V * V + uv], a1);
                    a2 = fmaf(pjr[r], ta[r * V * V + uv], a2);
                }
                val = fmaf(alpha, a1, Ag[s * V * V + uv]) + beta * a2;
            }
            vals[h2] = val;
        }
        dst[idx] = pk(vals[0], vals[1]);
    }
}

// ---------------- K3a: x3 GEMM  (64o x 128tv tile, 8x8 per thread, f32x2 o-pairs) ----------------
constexpr int KA_TV = 128;
constexpr int XA_F  = C * KA_TV;                 // 8192 floats (32KB)
constexpr int KA_SMEM_B = XA_F * 4 + S * C * 32 * 8;   // 32768 + 49152 = 81920

__global__ void __launch_bounds__(128, 2) k_x3(const float* __restrict__ x,
                                               const float* __restrict__ b3g)
{
    extern __shared__ float smf[];
    ull* wsu = reinterpret_cast<ull*>(smf + XA_F);
    int n = blockIdx.y, tv0 = blockIdx.x * KA_TV;
    int tid = threadIdx.x;
    int og = tid >> 4;          // 0..7  -> o rows og*8 .. og*8+7
    int tg = tid & 15;          // 0..15 -> tv cols tg*8 .. tg*8+7

    // W (all 3 s) into smem
    for (int i = tid; i < S * C * 32; i += 128) wsu[i] = g_w3p[i];
    // X tile
    {
        float4* dst = reinterpret_cast<float4*>(smf);
        for (int i = tid; i < C * KA_TV / 4; i += 128) {
            int c = i >> 5, j = i & 31;
            dst[i] = reinterpret_cast<const float4*>(
                x + ((size_t)(n * C + c)) * 6400 + tv0)[j];
        }
    }
    __syncthreads();

    #pragma unroll 1
    for (int s = 0; s < S; ++s) {
        ull acc[4][8];
        #pragma unroll
        for (int op = 0; op < 4; ++op) {
            int o0 = og * 8 + 2 * op;
            ull bp = pk(b3g[s * O + o0], b3g[s * O + o0 + 1]);
            #pragma unroll
            for (int j = 0; j < 8; ++j) acc[op][j] = bp;
        }
        const ull* wbase = wsu + (size_t)s * C * 32 + og * 4;
        #pragma unroll 4
        for (int c = 0; c < C; ++c) {
            const float4* xr = reinterpret_cast<const float4*>(smf + c * KA_TV + tg * 8);
            float4 xa = xr[0], xc = xr[1];
            ull xb[8];
            xb[0] = pk(xa.x, xa.x); xb[1] = pk(xa.y, xa.y);
            xb[2] = pk(xa.z, xa.z); xb[3] = pk(xa.w, xa.w);
            xb[4] = pk(xc.x, xc.x); xb[5] = pk(xc.y, xc.y);
            xb[6] = pk(xc.z, xc.z); xb[7] = pk(xc.w, xc.w);
            ulonglong2 wa = *reinterpret_cast<const ulonglong2*>(wbase + c * 32);
            ulonglong2 wb = *reinterpret_cast<const ulonglong2*>(wbase + c * 32 + 2);
            #pragma unroll
            for (int j = 0; j < 8; ++j) {
                acc[0][j] = f2fma(wa.x, xb[j], acc[0][j]);
                acc[1][j] = f2fma(wa.y, xb[j], acc[1][j]);
                acc[2][j] = f2fma(wb.x, xb[j], acc[2][j]);
                acc[3][j] = f2fma(wb.y, xb[j], acc[3][j]);
            }
        }
        // store to g_x3[s][n][o][tv]
        float* outb = g_x3 + ((size_t)(s * NB + n)) * O * 6400 + tv0 + tg * 8;
        #pragma unroll
        for (int op = 0; op < 4; ++op) {
            float lo[8], hi[8];
            #pragma unroll
            for (int j = 0; j < 8; ++j) upk(lo[j], hi[j], acc[op][j]);
            int o0 = og * 8 + 2 * op;
            float4* p0 = reinterpret_cast<float4*>(outb + (size_t)o0 * 6400);
            float4* p1 = reinterpret_cast<float4*>(outb + (size_t)(o0 + 1) * 6400);
            p0[0] = make_float4(lo[0], lo[1], lo[2], lo[3]);
            p0[1] = make_float4(lo[4], lo[5], lo[6], lo[7]);
            p1[0] = make_float4(hi[0], hi[1], hi[2], hi[3]);
            p1[1] = make_float4(hi[4], hi[5], hi[6], hi[7]);
        }
    }
}

// ---------------- K3b: y[n,o,t,u] = sum_{s,v} R3 * x3 ----------------
constexpr int KB_SMEM_B = 976 * 8 + 6400 * 4;    // 7808 + 25600 = 33408

__global__ void __launch_bounds__(256) k_y(float* __restrict__ ybuf)
{
    extern __shared__ float smf[];
    ull*   Rs = reinterpret_cast<ull*>(smf);     // 975 ull (pad to 976)
    float* xs = smf + 1952;                      // 6400 floats
    int n = blockIdx.y, o = blockIdx.x;
    int tid = threadIdx.x;                       // = t

    for (int i = tid; i < 975; i += 256) {
        int s = i / 325, r = i % 325;
        Rs[i] = g_R3[(((size_t)s * NB + n) * O + o) * 325 + r];
    }

    ull acc[13];
    #pragma unroll
    for (int k = 0; k < 13; ++k) acc[k] = 0ull;

    #pragma unroll 1
    for (int s = 0; s < S; ++s) {
        __syncthreads();
        {
            const float4* src = reinterpret_cast<const float4*>(
                g_x3 + (((size_t)(s * NB + n)) * O + o) * 6400);
            float4* dst = reinterpret_cast<float4*>(xs);
            for (int i = tid; i < 1600; i += 256) dst[i] = src[i];
        }
        __syncthreads();
        float xr[25];
        #pragma unroll
        for (int v = 0; v < 25; ++v) xr[v] = xs[tid * 25 + v];
        const ull* Rp = Rs + s * 325;
        #pragma unroll 5
        for (int v = 0; v < 25; ++v) {
            ull xb = pk(xr[v], xr[v]);
            #pragma unroll
            for (int k = 0; k < 13; ++k)
                acc[k] = f2fma(xb, Rp[k * 25 + v], acc[k]);
        }
    }

    __syncthreads();
    #pragma unroll
    for (int k = 0; k < 13; ++k) {
        float lo, hi; upk(lo, hi, acc[k]);
        xs[tid * 25 + 2 * k] = lo;
        if (k < 12) xs[tid * 25 + 2 * k + 1] = hi;
    }
    __syncthreads();
    {
        float4* outp = reinterpret_cast<float4*>(ybuf + ((size_t)(n * O + o)) * 6400);
        const float4* sp = reinterpret_cast<const float4*>(xs);
        for (int i = tid; i < 1600; i += 256) outp[i] = sp[i];
    }
}

// ---------------- K4: BN stats ----------------
__global__ void k_stats1(const float* __restrict__ ybuf)
{
    __shared__ float rs[256], rq[256];
    int o = blockIdx.x, chunk = blockIdx.y;
    int tid = threadIdx.x;
    float s = 0.f, s2 = 0.f;
    for (int nn = 0; nn < 4; ++nn) {
        const float* base = ybuf + ((size_t)((chunk * 4 + nn) * O + o)) * (T * V);
        for (int i = tid; i < T * V; i += 256) {
            float v = base[i];
            s += v; s2 = fmaf(v, v, s2);
        }
    }
    rs[tid] = s; rq[tid] = s2;
    __syncthreads();
    for (int st = 128; st > 0; st >>= 1) {
        if (tid < st) { rs[tid] += rs[tid + st]; rq[tid] += rq[tid + st]; }
        __syncthreads();
    }
    if (tid == 0) g_part[o * 16 + chunk] = make_float2(rs[0], rq[0]);
}

__global__ void k_stats2(const float* __restrict__ bnw, const float* __restrict__ bnb)
{
    int o = threadIdx.x;
    float s = 0.f, s2 = 0.f;
    for (int c = 0; c < 16; ++c) { float2 p = g_part[o * 16 + c]; s += p.x; s2 += p.y; }
    float M = (float)(NB * T * V);
    float mean = s / M;
    float var  = s2 / M - mean * mean;
    float sc = bnw[o] * rsqrtf(var + 1e-5f);
    g_stats[o] = make_float2(sc, bnb[o] - mean * sc);
}

// ---------------- K5: BN apply + residual + relu ----------------
__global__ void k_final(float4* __restrict__ ybuf, const float4* __restrict__ x)
{
    int idx = blockIdx.x * 256 + threadIdx.x;
    int o = (idx / (T * V / 4)) & 63;
    float2 ss = g_stats[o];
    float4 y = ybuf[idx], xx = x[idx];
    y.x = fmaxf(fmaf(y.x, ss.x, ss.y) + xx.x, 0.f);
    y.y = fmaxf(fmaf(y.y, ss.x, ss.y) + xx.y, 0.f);
    y.z = fmaxf(fmaf(y.z, ss.x, ss.y) + xx.z, 0.f);
    y.w = fmaxf(fmaf(y.w, ss.x, ss.y) + xx.w, 0.f);
    ybuf[idx] = y;
}

// ---------------- launch ----------------
extern "C" void kernel_launch(void* const* d_in, const int* in_sizes, int n_in,
                              void* d_out, int out_size)
{
    (void)in_sizes; (void)n_in; (void)out_size;
    const float* x    = (const float*)d_in[0];
    const float* A    = (const float*)d_in[1];
    const float* alph = (const float*)d_in[2];
    const float* w1   = (const float*)d_in[3];
    const float* b1   = (const float*)d_in[4];
    const float* w2   = (const float*)d_in[5];
    const float* b2   = (const float*)d_in[6];
    const float* w3   = (const float*)d_in[7];
    const float* b3   = (const float*)d_in[8];
    const float* w4   = (const float*)d_in[9];
    const float* b4   = (const float*)d_in[10];
    const float* pw1  = (const float*)d_in[11];
    const float* pb1  = (const float*)d_in[12];
    const float* pw2  = (const float*)d_in[13];
    const float* pb2  = (const float*)d_in[14];
    const float* dww  = (const float*)d_in[15];
    const float* pjw  = (const float*)d_in[16];
    const float* beta = (const float*)d_in[17];
    const float* gamma= (const float*)d_in[18];
    const float* bnw  = (const float*)d_in[19];
    const float* bnb  = (const float*)d_in[20];
    float* out = (float*)d_out;

    cudaFuncSetAttribute(k_R,  cudaFuncAttributeMaxDynamicSharedMemorySize, 15800 * 4);
    cudaFuncSetAttribute(k_x3, cudaFuncAttributeMaxDynamicSharedMemorySize, KA_SMEM_B);

    k_xm<<<NB * C, 256>>>(x);
    k_w3p<<<S * C * 32 / 256, 256>>>(w3);
    k_R<<<dim3(NB, S), 256, 15800 * 4>>>(A, alph, w1, b1, w2, b2, w4, b4,
                                         pw1, pb1, pw2, pb2, dww, pjw, beta, gamma);
    k_x3<<<dim3(T * V / KA_TV, NB), 128, KA_SMEM_B>>>(x, b3);
    k_y<<<dim3(O, NB), 256, KB_SMEM_B>>>(out);
    k_stats1<<<dim3(O, 16), 256>>>(out);
    k_stats2<<<1, O>>>(bnw, bnb);
    k_final<<<(NB * C * T * V) / 1024, 256>>>((float4*)out, (const float4*)x);
}

// round 7
// speedup vs baseline: 1.8485x; 1.0169x over previous
#include <cuda_runtime.h>

#define NB 64
#define C  64
#define T  256
#define V  25
#define S  3
#define R  8
#define O  64

typedef unsigned long long ull;

// ---------------- scratch ----------------
__device__ float  g_xm[NB * C * V];
__device__ ull    g_w3d[S * C * O];                     // pk(w,w) dup-packed, [s][c][o]
__device__ ull    g_R3[(size_t)S * NB * O * 13 * 25];   // pk(R[2k][v], R[2k+1][v])
__device__ float  g_x3[(size_t)S * NB * O * T * V];     // x3[s][n][o][t*25+v]
__device__ float2 g_stats[O];
__device__ float2 g_part2[O * NB];

// ---------------- f32x2 helpers ----------------
__device__ __forceinline__ ull pk(float lo, float hi) {
    ull r; asm("mov.b64 %0, {%1,%2};" : "=l"(r) : "f"(lo), "f"(hi)); return r;
}
__device__ __forceinline__ void upk(float& lo, float& hi, ull v) {
    asm("mov.b64 {%0,%1}, %2;" : "=f"(lo), "=f"(hi) : "l"(v));
}
__device__ __forceinline__ ull f2fma(ull a, ull b, ull c) {
    ull d; asm("fma.rn.f32x2 %0, %1, %2, %3;" : "=l"(d) : "l"(a), "l"(b), "l"(c)); return d;
}

// ---------------- K1: xm[n,c,v] = mean_t x ----------------
__global__ void k_xm(const float* __restrict__ x) {
    __shared__ float red[256 * V];
    int bx  = blockIdx.x;
    int tid = threadIdx.x;
    const float* row = x + (size_t)bx * T * V + (size_t)tid * V;
    #pragma unroll
    for (int v = 0; v < V; ++v) red[tid * V + v] = row[v];
    __syncthreads();
    for (int st = 128; st > 0; st >>= 1) {
        if (tid < st) {
            #pragma unroll
            for (int v = 0; v < V; ++v) red[tid * V + v] += red[(tid + st) * V + v];
        }
        __syncthreads();
    }
    if (tid < V) g_xm[bx * V + tid] = red[tid] * (1.0f / T);
}

// ---------------- K1b: dup-pack w3, layout [s][c][o] ----------------
__global__ void k_w3d(const float* __restrict__ w3g) {
    int idx = blockIdx.x * 256 + threadIdx.x;        // < S*C*O
    int s = idx / (C * O), rem = idx % (C * O), c = rem >> 6, o = rem & 63;
    float w = w3g[(s * O + o) * C + c];
    g_w3d[idx] = pk(w, w);
}

// ---------------- K2: build R3 (u-pair packed) ----------------
__global__ void k_R(const float* __restrict__ Ag,   const float* __restrict__ alphag,
                    const float* __restrict__ w1g,  const float* __restrict__ b1g,
                    const float* __restrict__ w2g,  const float* __restrict__ b2g,
                    const float* __restrict__ w4g,  const float* __restrict__ b4g,
                    const float* __restrict__ pw1g, const float* __restrict__ pb1g,
                    const float* __restrict__ pw2g, const float* __restrict__ pb2g,
                    const float* __restrict__ dwwg, const float* __restrict__ pjwg,
                    const float* __restrict__ betag,const float* __restrict__ gammag)
{
    extern __shared__ float sm[];
    float* q1s = sm;            // 5000 (reused as ta)
    float* qas = sm + 5000;     // 5000
    float* ds  = sm + 10000;    // 5000
    float* x1s = sm + 15000;    // 200
    float* x2s = sm + 15200;    // 200
    float* as_ = sm + 15400;    // 200
    float* bs_ = sm + 15600;    // 200

    int n = blockIdx.x, s = blockIdx.y;
    int tid = threadIdx.x;
    const float* xm = g_xm + n * (C * V);

    for (int idx = tid; idx < R * V; idx += blockDim.x) {
        int r = idx / V, u = idx % V;
        float s1 = b1g[s * R + r], s2 = b2g[s * R + r];
        const float* w1r = w1g + (s * R + r) * C;
        const float* w2r = w2g + (s * R + r) * C;
        for (int c = 0; c < C; ++c) {
            float xv = xm[c * V + u];
            s1 = fmaf(w1r[c], xv, s1);
            s2 = fmaf(w2r[c], xv, s2);
        }
        x1s[idx] = s1; x2s[idx] = s2;
    }
    __syncthreads();
    for (int idx = tid; idx < R * V; idx += blockDim.x) {
        int r = idx / V, u = idx % V;
        const float* p1 = pw1g + (s * R + r) * (2 * R);
        float av = 0.f, bv = 0.f;
        #pragma unroll
        for (int p = 0; p < R; ++p) {
            av = fmaf(p1[p],     x2s[p * V + u], av);
            bv = fmaf(p1[R + p], x2s[p * V + u], bv);
        }
        as_[idx] = av; bs_[idx] = bv;
    }
    __syncthreads();
    for (int idx = tid; idx < R * V * V; idx += blockDim.x) {
        int r = idx / (V * V), uv = idx % (V * V), u = uv / V, v = uv % V;
        q1s[idx] = tanhf(x1s[r * V + u] - x2s[r * V + v]);
    }
    __syncthreads();
    float gma = gammag[s];
    for (int uv = tid; uv < V * V; uv += blockDim.x) {
        int u = uv / V, v = uv % V;
        float h[R];
        #pragma unroll
        for (int p = 0; p < R; ++p)
            h[p] = fmaxf(as_[p * V + u] + bs_[p * V + v] + pb1g[s * R + p], 0.f);
        #pragma unroll
        for (int r = 0; r < R; ++r) {
            float q2 = pb2g[s * R + r];
            const float* p2 = pw2g + (s * R + r) * R;
            #pragma unroll
            for (int p = 0; p < R; ++p) q2 = fmaf(p2[p], h[p], q2);
            qas[r * V * V + uv] = q1s[r * V * V + uv] + gma * q2;
        }
    }
    __syncthreads();
    for (int idx = tid; idx < R * V * V; idx += blockDim.x) {
        int r = idx / (V * V), uv = idx % (V * V), u = uv / V, v = uv % V;
        const float* kw = dwwg + (s * R + r) * 9;
        float acc = 0.f;
        #pragma unroll
        for (int ki = 0; ki < 3; ++ki) {
            int uu = u + ki - 1; if (uu < 0 || uu >= V) continue;
            #pragma unroll
            for (int kj = 0; kj < 3; ++kj) {
                int vv = v + kj - 1; if (vv < 0 || vv >= V) continue;
                acc = fmaf(q1s[r * V * V + uu * V + vv], kw[ki * 3 + kj], acc);
            }
        }
        ds[idx] = acc;
    }
    __syncthreads();
    for (int idx = tid; idx < R * V * V; idx += blockDim.x) {
        int r = idx / (V * V), uv = idx % (V * V), u = uv / V, v = uv % V;
        float acc = 0.f;
        for (int ki = -1; ki <= 1; ++ki) {
            int uu = u + ki; if (uu < 0 || uu >= V) continue;
            for (int kj = -1; kj <= 1; ++kj) {
                int vv = v + kj; if (vv < 0 || vv >= V) continue;
                acc += ds[r * V * V + uu * V + vv];
            }
        }
        q1s[idx] = tanhf(acc * (1.f / 9.f));
    }
    __syncthreads();
    float alpha = alphag[0], beta = betag[s];
    const float* ta = q1s;
    ull* dst = g_R3 + ((size_t)(s * NB + n)) * O * 325;
    for (int idx = tid; idx < O * 325; idx += blockDim.x) {
        int o = idx / 325, kv = idx % 325, k = kv / 25, v = kv % 25;
        const float* w4r = w4g + (s * O + o) * R;
        const float* pjr = pjwg + (s * O + o) * R;
        float vals[2];
        #pragma unroll
        for (int h2 = 0; h2 < 2; ++h2) {
            int u = 2 * k + h2;
            float val = 0.f;
            if (u < V) {
                int uv = u * V + v;
                float a1 = b4g[s * O + o], a2 = 0.f;
                #pragma unroll
                for (int r = 0; r < R; ++r) {
                    a1 = fmaf(w4r[r], qas[r * V * V + uv], a1);
                    a2 = fmaf(pjr[r], ta[r * V * V + uv], a2);
                }
                val = fmaf(alpha, a1, Ag[s * V * V + uv]) + beta * a2;
            }
            vals[h2] = val;
        }
        dst[idx] = pk(vals[0], vals[1]);
    }
}

// ---------------- K3a: x3 GEMM (64o x 256tv tile, 8o x 8tv per thread, tv-packed) ----------------
constexpr int TVT = 256;
constexpr int XA_F = C * TVT;                          // 16384 floats = 64KB
constexpr int KA_SMEM_B = XA_F * 4 + C * O * 8;        // 65536 + 32768 = 98304

__global__ void __launch_bounds__(256, 2) k_x3(const float* __restrict__ x,
                                               const float* __restrict__ b3g)
{
    extern __shared__ float smf[];
    ull* ws = reinterpret_cast<ull*>(smf + XA_F);
    int n = blockIdx.y, tv0 = blockIdx.x * TVT;
    int tid = threadIdx.x;
    int og = tid >> 5;          // warp id 0..7 -> o rows og*8..og*8+7
    int tg = tid & 31;          // lane -> tv cols tg*8..tg*8+7

    // load x tile [c][256]
    for (int i = tid; i < C * TVT / 4; i += 256) {
        int c = i >> 6, j = i & 63;
        reinterpret_cast<float4*>(smf)[i] =
            reinterpret_cast<const float4*>(x + ((size_t)(n * C + c)) * 6400 + tv0)[j];
    }

    #pragma unroll 1
    for (int s = 0; s < S; ++s) {
        __syncthreads();
        for (int i = tid; i < C * O; i += 256) ws[i] = g_w3d[s * C * O + i];
        __syncthreads();

        ull acc[8][4];
        #pragma unroll
        for (int o = 0; o < 8; ++o) {
            float b = b3g[s * O + og * 8 + o];
            ull bp = pk(b, b);
            #pragma unroll
            for (int j = 0; j < 4; ++j) acc[o][j] = bp;
        }

        #pragma unroll 4
        for (int c = 0; c < C; ++c) {
            const ull* xr = reinterpret_cast<const ull*>(smf + c * TVT + tg * 8);
            ulonglong2 xa = reinterpret_cast<const ulonglong2*>(xr)[0];
            ulonglong2 xb = reinterpret_cast<const ulonglong2*>(xr)[1];
            ull xv0 = xa.x, xv1 = xa.y, xv2 = xb.x, xv3 = xb.y;
            const ull* wb = ws + c * O + og * 8;
            ulonglong2 w0 = reinterpret_cast<const ulonglong2*>(wb)[0];
            ulonglong2 w1 = reinterpret_cast<const ulonglong2*>(wb)[1];
            ulonglong2 w2 = reinterpret_cast<const ulonglong2*>(wb)[2];
            ulonglong2 w3q = reinterpret_cast<const ulonglong2*>(wb)[3];
            ull wv[8] = {w0.x, w0.y, w1.x, w1.y, w2.x, w2.y, w3q.x, w3q.y};
            #pragma unroll
            for (int o = 0; o < 8; ++o) {
                acc[o][0] = f2fma(wv[o], xv0, acc[o][0]);
                acc[o][1] = f2fma(wv[o], xv1, acc[o][1]);
                acc[o][2] = f2fma(wv[o], xv2, acc[o][2]);
                acc[o][3] = f2fma(wv[o], xv3, acc[o][3]);
            }
        }

        float* outb = g_x3 + ((size_t)(s * NB + n)) * O * 6400 + tv0 + tg * 8;
        #pragma unroll
        for (int o = 0; o < 8; ++o) {
            float4 f0, f1;
            upk(f0.x, f0.y, acc[o][0]);
            upk(f0.z, f0.w, acc[o][1]);
            upk(f1.x, f1.y, acc[o][2]);
            upk(f1.z, f1.w, acc[o][3]);
            float* op = outb + (size_t)(og * 8 + o) * 6400;
            reinterpret_cast<float4*>(op)[0] = f0;
            reinterpret_cast<float4*>(op)[1] = f1;
        }
    }
}

// ---------------- K3b: y + fused BN partial stats ----------------
constexpr int KB_SMEM_B = 976 * 8 + 6400 * 4 + 512 * 4;  // 7808 + 25600 + 2048

__global__ void __launch_bounds__(256) k_y(float* __restrict__ ybuf)
{
    extern __shared__ float smf[];
    ull*   Rs = reinterpret_cast<ull*>(smf);     // 975 ull (pad to 976)
    float* xs = smf + 1952;                      // 6400 floats
    float* rs = smf + 1952 + 6400;               // 256
    float* rq = rs + 256;                        // 256
    int n = blockIdx.y, o = blockIdx.x;
    int tid = threadIdx.x;                       // = t

    for (int i = tid; i < 975; i += 256) {
        int s = i / 325, r = i % 325;
        Rs[i] = g_R3[(((size_t)s * NB + n) * O + o) * 325 + r];
    }

    ull acc[13];
    #pragma unroll
    for (int k = 0; k < 13; ++k) acc[k] = 0ull;

    #pragma unroll 1
    for (int s = 0; s < S; ++s) {
        __syncthreads();
        {
            const float4* src = reinterpret_cast<const float4*>(
                g_x3 + (((size_t)(s * NB + n)) * O + o) * 6400);
            float4* dst = reinterpret_cast<float4*>(xs);
            for (int i = tid; i < 1600; i += 256) dst[i] = src[i];
        }
        __syncthreads();
        float xr[25];
        #pragma unroll
        for (int v = 0; v < 25; ++v) xr[v] = xs[tid * 25 + v];
        const ull* Rp = Rs + s * 325;
        #pragma unroll 5
        for (int v = 0; v < 25; ++v) {
            ull xb = pk(xr[v], xr[v]);
            #pragma unroll
            for (int k = 0; k < 13; ++k)
                acc[k] = f2fma(xb, Rp[k * 25 + v], acc[k]);
        }
    }

    // unpack, thread-local stats
    float zv[25];
    float sum = 0.f, sq = 0.f;
    #pragma unroll
    for (int k = 0; k < 13; ++k) {
        float lo, hi; upk(lo, hi, acc[k]);
        zv[2 * k] = lo;
        if (k < 12) zv[2 * k + 1] = hi;
    }
    #pragma unroll
    for (int u = 0; u < 25; ++u) { sum += zv[u]; sq = fmaf(zv[u], zv[u], sq); }

    __syncthreads();
    #pragma unroll
    for (int u = 0; u < 25; ++u) xs[tid * 25 + u] = zv[u];
    rs[tid] = sum; rq[tid] = sq;
    __syncthreads();
    {
        float4* outp = reinterpret_cast<float4*>(ybuf + ((size_t)(n * O + o)) * 6400);
        const float4* sp = reinterpret_cast<const float4*>(xs);
        for (int i = tid; i < 1600; i += 256) outp[i] = sp[i];
    }
    for (int st = 128; st > 0; st >>= 1) {
        if (tid < st) { rs[tid] += rs[tid + st]; rq[tid] += rq[tid + st]; }
        __syncthreads();
    }
    if (tid == 0) g_part2[o * NB + n] = make_float2(rs[0], rq[0]);
}

// ---------------- K4: BN stats combine ----------------
__global__ void k_stats2(const float* __restrict__ bnw, const float* __restrict__ bnb)
{
    int o = threadIdx.x;
    float s = 0.f, s2 = 0.f;
    for (int nn = 0; nn < NB; ++nn) {
        float2 p = g_part2[o * NB + nn];
        s += p.x; s2 += p.y;
    }
    float M = (float)(NB * T * V);
    float mean = s / M;
    float var  = s2 / M - mean * mean;
    float sc = bnw[o] * rsqrtf(var + 1e-5f);
    g_stats[o] = make_float2(sc, bnb[o] - mean * sc);
}

// ---------------- K5: BN apply + residual + relu ----------------
__global__ void k_final(float4* __restrict__ ybuf, const float4* __restrict__ x)
{
    int idx = blockIdx.x * 256 + threadIdx.x;
    int o = (idx / (T * V / 4)) & 63;
    float2 ss = g_stats[o];
    float4 y = ybuf[idx], xx = x[idx];
    y.x = fmaxf(fmaf(y.x, ss.x, ss.y) + xx.x, 0.f);
    y.y = fmaxf(fmaf(y.y, ss.x, ss.y) + xx.y, 0.f);
    y.z = fmaxf(fmaf(y.z, ss.x, ss.y) + xx.z, 0.f);
    y.w = fmaxf(fmaf(y.w, ss.x, ss.y) + xx.w, 0.f);
    ybuf[idx] = y;
}

// ---------------- launch ----------------
extern "C" void kernel_launch(void* const* d_in, const int* in_sizes, int n_in,
                              void* d_out, int out_size)
{
    (void)in_sizes; (void)n_in; (void)out_size;
    const float* x    = (const float*)d_in[0];
    const float* A    = (const float*)d_in[1];
    const float* alph = (const float*)d_in[2];
    const float* w1   = (const float*)d_in[3];
    const float* b1   = (const float*)d_in[4];
    const float* w2   = (const float*)d_in[5];
    const float* b2   = (const float*)d_in[6];
    const float* w3   = (const float*)d_in[7];
    const float* b3   = (const float*)d_in[8];
    const float* w4   = (const float*)d_in[9];
    const float* b4   = (const float*)d_in[10];
    const float* pw1  = (const float*)d_in[11];
    const float* pb1  = (const float*)d_in[12];
    const float* pw2  = (const float*)d_in[13];
    const float* pb2  = (const float*)d_in[14];
    const float* dww  = (const float*)d_in[15];
    const float* pjw  = (const float*)d_in[16];
    const float* beta = (const float*)d_in[17];
    const float* gamma= (const float*)d_in[18];
    const float* bnw  = (const float*)d_in[19];
    const float* bnb  = (const float*)d_in[20];
    float* out = (float*)d_out;

    cudaFuncSetAttribute(k_R,  cudaFuncAttributeMaxDynamicSharedMemorySize, 15800 * 4);
    cudaFuncSetAttribute(k_x3, cudaFuncAttributeMaxDynamicSharedMemorySize, KA_SMEM_B);
    cudaFuncSetAttribute(k_y,  cudaFuncAttributeMaxDynamicSharedMemorySize, KB_SMEM_B);

    k_xm<<<NB * C, 256>>>(x);
    k_w3d<<<S * C * O / 256, 256>>>(w3);
    k_R<<<dim3(NB, S), 256, 15800 * 4>>>(A, alph, w1, b1, w2, b2, w4, b4,
                                         pw1, pb1, pw2, pb2, dww, pjw, beta, gamma);
    k_x3<<<dim3(T * V / TVT, NB), 256, KA_SMEM_B>>>(x, b3);
    k_y<<<dim3(O, NB), 256, KB_SMEM_B>>>(out);
    k_stats2<<<1, O>>>(bnw, bnb);
    k_final<<<(NB * C * T * V) / 1024, 256>>>((float4*)out, (const float4*)x);
}

// round 8
// speedup vs baseline: 1.9616x; 1.0612x over previous
#include <cuda_runtime.h>

#define NB 64
#define C  64
#define T  256
#define V  25
#define S  3
#define R  8
#define O  64

typedef unsigned long long ull;

// ---------------- scratch ----------------
__device__ float  g_xm[NB * C * V];
__device__ ull    g_w3d[S * C * O];                     // pk(w,w) dup-packed, [s][c][o]
__device__ float  g_R4[(size_t)S * NB * O * V * V];     // scalar R[s][n][o][u*25+v]
__device__ float  g_x3[(size_t)S * NB * O * T * V];     // x3[s][n][o][t*25+v]
__device__ float2 g_stats[O];
__device__ float2 g_part2[O * NB];

// ---------------- f32x2 helpers ----------------
__device__ __forceinline__ ull pk(float lo, float hi) {
    ull r; asm("mov.b64 %0, {%1,%2};" : "=l"(r) : "f"(lo), "f"(hi)); return r;
}
__device__ __forceinline__ void upk(float& lo, float& hi, ull v) {
    asm("mov.b64 {%0,%1}, %2;" : "=f"(lo), "=f"(hi) : "l"(v));
}
__device__ __forceinline__ ull f2fma(ull a, ull b, ull c) {
    ull d; asm("fma.rn.f32x2 %0, %1, %2, %3;" : "=l"(d) : "l"(a), "l"(b), "l"(c)); return d;
}

// ---------------- K1: xm[n,c,v] = mean_t x ----------------
__global__ void k_xm(const float* __restrict__ x) {
    __shared__ float red[256 * V];
    int bx  = blockIdx.x;
    int tid = threadIdx.x;
    const float* row = x + (size_t)bx * T * V + (size_t)tid * V;
    #pragma unroll
    for (int v = 0; v < V; ++v) red[tid * V + v] = row[v];
    __syncthreads();
    for (int st = 128; st > 0; st >>= 1) {
        if (tid < st) {
            #pragma unroll
            for (int v = 0; v < V; ++v) red[tid * V + v] += red[(tid + st) * V + v];
        }
        __syncthreads();
    }
    if (tid < V) g_xm[bx * V + tid] = red[tid] * (1.0f / T);
}

// ---------------- K1b: dup-pack w3, layout [s][c][o] ----------------
__global__ void k_w3d(const float* __restrict__ w3g) {
    int idx = blockIdx.x * 256 + threadIdx.x;        // < S*C*O
    int s = idx / (C * O), rem = idx % (C * O), c = rem >> 6, o = rem & 63;
    float w = w3g[(s * O + o) * C + c];
    g_w3d[idx] = pk(w, w);
}

// ---------------- K2: build scalar R4 ----------------
__global__ void k_R(const float* __restrict__ Ag,   const float* __restrict__ alphag,
                    const float* __restrict__ w1g,  const float* __restrict__ b1g,
                    const float* __restrict__ w2g,  const float* __restrict__ b2g,
                    const float* __restrict__ w4g,  const float* __restrict__ b4g,
                    const float* __restrict__ pw1g, const float* __restrict__ pb1g,
                    const float* __restrict__ pw2g, const float* __restrict__ pb2g,
                    const float* __restrict__ dwwg, const float* __restrict__ pjwg,
                    const float* __restrict__ betag,const float* __restrict__ gammag)
{
    extern __shared__ float sm[];
    float* q1s = sm;            // 5000 (reused as ta)
    float* qas = sm + 5000;     // 5000
    float* ds  = sm + 10000;    // 5000
    float* x1s = sm + 15000;    // 200
    float* x2s = sm + 15200;    // 200
    float* as_ = sm + 15400;    // 200
    float* bs_ = sm + 15600;    // 200

    int n = blockIdx.x, s = blockIdx.y;
    int tid = threadIdx.x;
    const float* xm = g_xm + n * (C * V);

    for (int idx = tid; idx < R * V; idx += blockDim.x) {
        int r = idx / V, u = idx % V;
        float s1 = b1g[s * R + r], s2 = b2g[s * R + r];
        const float* w1r = w1g + (s * R + r) * C;
        const float* w2r = w2g + (s * R + r) * C;
        for (int c = 0; c < C; ++c) {
            float xv = xm[c * V + u];
            s1 = fmaf(w1r[c], xv, s1);
            s2 = fmaf(w2r[c], xv, s2);
        }
        x1s[idx] = s1; x2s[idx] = s2;
    }
    __syncthreads();
    for (int idx = tid; idx < R * V; idx += blockDim.x) {
        int r = idx / V, u = idx % V;
        const float* p1 = pw1g + (s * R + r) * (2 * R);
        float av = 0.f, bv = 0.f;
        #pragma unroll
        for (int p = 0; p < R; ++p) {
            av = fmaf(p1[p],     x2s[p * V + u], av);
            bv = fmaf(p1[R + p], x2s[p * V + u], bv);
        }
        as_[idx] = av; bs_[idx] = bv;
    }
    __syncthreads();
    for (int idx = tid; idx < R * V * V; idx += blockDim.x) {
        int r = idx / (V * V), uv = idx % (V * V), u = uv / V, v = uv % V;
        q1s[idx] = tanhf(x1s[r * V + u] - x2s[r * V + v]);
    }
    __syncthreads();
    float gma = gammag[s];
    for (int uv = tid; uv < V * V; uv += blockDim.x) {
        int u = uv / V, v = uv % V;
        float h[R];
        #pragma unroll
        for (int p = 0; p < R; ++p)
            h[p] = fmaxf(as_[p * V + u] + bs_[p * V + v] + pb1g[s * R + p], 0.f);
        #pragma unroll
        for (int r = 0; r < R; ++r) {
            float q2 = pb2g[s * R + r];
            const float* p2 = pw2g + (s * R + r) * R;
            #pragma unroll
            for (int p = 0; p < R; ++p) q2 = fmaf(p2[p], h[p], q2);
            qas[r * V * V + uv] = q1s[r * V * V + uv] + gma * q2;
        }
    }
    __syncthreads();
    for (int idx = tid; idx < R * V * V; idx += blockDim.x) {
        int r = idx / (V * V), uv = idx % (V * V), u = uv / V, v = uv % V;
        const float* kw = dwwg + (s * R + r) * 9;
        float acc = 0.f;
        #pragma unroll
        for (int ki = 0; ki < 3; ++ki) {
            int uu = u + ki - 1; if (uu < 0 || uu >= V) continue;
            #pragma unroll
            for (int kj = 0; kj < 3; ++kj) {
                int vv = v + kj - 1; if (vv < 0 || vv >= V) continue;
                acc = fmaf(q1s[r * V * V + uu * V + vv], kw[ki * 3 + kj], acc);
            }
        }
        ds[idx] = acc;
    }
    __syncthreads();
    for (int idx = tid; idx < R * V * V; idx += blockDim.x) {
        int r = idx / (V * V), uv = idx % (V * V), u = uv / V, v = uv % V;
        float acc = 0.f;
        for (int ki = -1; ki <= 1; ++ki) {
            int uu = u + ki; if (uu < 0 || uu >= V) continue;
            for (int kj = -1; kj <= 1; ++kj) {
                int vv = v + kj; if (vv < 0 || vv >= V) continue;
                acc += ds[r * V * V + uu * V + vv];
            }
        }
        q1s[idx] = tanhf(acc * (1.f / 9.f));
    }
    __syncthreads();
    float alpha = alphag[0], beta = betag[s];
    const float* ta = q1s;
    float* dst = g_R4 + ((size_t)(s * NB + n)) * O * 625;
    for (int idx = tid; idx < O * 625; idx += blockDim.x) {
        int o = idx / 625, uv = idx % 625;
        float a1 = b4g[s * O + o], a2 = 0.f;
        const float* w4r = w4g + (s * O + o) * R;
        const float* pjr = pjwg + (s * O + o) * R;
        #pragma unroll
        for (int r = 0; r < R; ++r) {
            a1 = fmaf(w4r[r], qas[r * V * V + uv], a1);
            a2 = fmaf(pjr[r], ta[r * V * V + uv], a2);
        }
        dst[idx] = fmaf(alpha, a1, Ag[s * V * V + uv]) + beta * a2;
    }
}

// ---------------- K3a: x3 GEMM (64o x 256tv tile, contiguous lane mapping) ----------------
constexpr int TVT = 256;
constexpr int XA_F = C * TVT;                          // 16384 floats = 64KB
constexpr int KA_SMEM_B = XA_F * 4 + C * O * 8;        // 65536 + 32768 = 98304

__global__ void __launch_bounds__(256, 2) k_x3(const float* __restrict__ x,
                                               const float* __restrict__ b3g)
{
    extern __shared__ float smf[];
    ull* ws = reinterpret_cast<ull*>(smf + XA_F);
    int n = blockIdx.y, tv0 = blockIdx.x * TVT;
    int tid = threadIdx.x;
    int og = tid >> 5;          // warp id 0..7 -> o rows og*8..og*8+7
    int tg = tid & 31;          // lane -> tv cols {tg*4..tg*4+3} and {128+tg*4..+3}

    // load x tile [c][256]
    for (int i = tid; i < C * TVT / 4; i += 256) {
        int c = i >> 6, j = i & 63;
        reinterpret_cast<float4*>(smf)[i] =
            reinterpret_cast<const float4*>(x + ((size_t)(n * C + c)) * 6400 + tv0)[j];
    }

    #pragma unroll 1
    for (int s = 0; s < S; ++s) {
        __syncthreads();
        for (int i = tid; i < C * O; i += 256) ws[i] = g_w3d[s * C * O + i];
        __syncthreads();

        ull acc[8][4];
        #pragma unroll
        for (int o = 0; o < 8; ++o) {
            float b = b3g[s * O + og * 8 + o];
            ull bp = pk(b, b);
            #pragma unroll
            for (int j = 0; j < 4; ++j) acc[o][j] = bp;
        }

        #pragma unroll 4
        for (int c = 0; c < C; ++c) {
            ulonglong2 xa = *reinterpret_cast<const ulonglong2*>(smf + c * TVT + tg * 4);
            ulonglong2 xb = *reinterpret_cast<const ulonglong2*>(smf + c * TVT + 128 + tg * 4);
            ull xv0 = xa.x, xv1 = xa.y, xv2 = xb.x, xv3 = xb.y;
            const ull* wb = ws + c * O + og * 8;
            ulonglong2 w0 = reinterpret_cast<const ulonglong2*>(wb)[0];
            ulonglong2 w1 = reinterpret_cast<const ulonglong2*>(wb)[1];
            ulonglong2 w2 = reinterpret_cast<const ulonglong2*>(wb)[2];
            ulonglong2 w3q = reinterpret_cast<const ulonglong2*>(wb)[3];
            ull wv[8] = {w0.x, w0.y, w1.x, w1.y, w2.x, w2.y, w3q.x, w3q.y};
            #pragma unroll
            for (int o = 0; o < 8; ++o) {
                acc[o][0] = f2fma(wv[o], xv0, acc[o][0]);
                acc[o][1] = f2fma(wv[o], xv1, acc[o][1]);
                acc[o][2] = f2fma(wv[o], xv2, acc[o][2]);
                acc[o][3] = f2fma(wv[o], xv3, acc[o][3]);
            }
        }

        float* outb = g_x3 + ((size_t)(s * NB + n)) * O * 6400 + tv0;
        #pragma unroll
        for (int o = 0; o < 8; ++o) {
            float4 f0, f1;
            upk(f0.x, f0.y, acc[o][0]);
            upk(f0.z, f0.w, acc[o][1]);
            upk(f1.x, f1.y, acc[o][2]);
            upk(f1.z, f1.w, acc[o][3]);
            float* op = outb + (size_t)(og * 8 + o) * 6400;
            *reinterpret_cast<float4*>(op + tg * 4)       = f0;
            *reinterpret_cast<float4*>(op + 128 + tg * 4) = f1;
        }
    }
}

// ---------------- K3b: y = R-contraction, 4t/thread, fused BN partials ----------------
constexpr int KY_SMEM_B = (6400 + 1875 + 128) * 4;     // 33612 bytes

__global__ void __launch_bounds__(64) k_y(float* __restrict__ ybuf)
{
    extern __shared__ float smf[];
    float* xs = smf;            // 6400
    float* Rs = smf + 6400;     // 1875
    float* rs = smf + 8275;     // 64
    float* rq = smf + 8339;     // 64
    int n = blockIdx.y, o = blockIdx.x;
    int tid = threadIdx.x;      // 0..63, t quad = {tid, tid+64, tid+128, tid+192}

    // stage R (all 3 s), scalar
    for (int i = tid; i < S * 625; i += 64) {
        int s = i / 625, r = i % 625;
        Rs[i] = g_R4[(((size_t)s * NB + n) * O + o) * 625 + r];
    }

    ull acc[25][2];
    #pragma unroll
    for (int u = 0; u < 25; ++u) { acc[u][0] = 0ull; acc[u][1] = 0ull; }

    #pragma unroll 1
    for (int s = 0; s < S; ++s) {
        __syncthreads();
        {
            const float4* src = reinterpret_cast<const float4*>(
                g_x3 + (((size_t)(s * NB + n)) * O + o) * 6400);
            float4* dst = reinterpret_cast<float4*>(xs);
            for (int i = tid; i < 1600; i += 64) dst[i] = src[i];
        }
        __syncthreads();
        const float* Rp = Rs + s * 625;
        #pragma unroll 1
        for (int v = 0; v < 25; ++v) {
            float a0 = xs[tid * 25 + v];
            float a1 = xs[(tid + 64) * 25 + v];
            float a2 = xs[(tid + 128) * 25 + v];
            float a3 = xs[(tid + 192) * 25 + v];
            ull x0 = pk(a0, a1), x1 = pk(a2, a3);
            #pragma unroll
            for (int u = 0; u < 25; ++u) {
                float rv = Rp[u * 25 + v];
                ull rd = pk(rv, rv);
                acc[u][0] = f2fma(x0, rd, acc[u][0]);
                acc[u][1] = f2fma(x1, rd, acc[u][1]);
            }
        }
    }

    // unpack + thread-local stats + stage into xs
    float sum = 0.f, sq = 0.f;
    __syncthreads();
    #pragma unroll
    for (int u = 0; u < 25; ++u) {
        float z0, z1, z2, z3;
        upk(z0, z1, acc[u][0]);
        upk(z2, z3, acc[u][1]);
        xs[tid * 25 + u]         = z0;
        xs[(tid + 64) * 25 + u]  = z1;
        xs[(tid + 128) * 25 + u] = z2;
        xs[(tid + 192) * 25 + u] = z3;
        sum += z0 + z1 + z2 + z3;
        sq  = fmaf(z0, z0, sq); sq = fmaf(z1, z1, sq);
        sq  = fmaf(z2, z2, sq); sq = fmaf(z3, z3, sq);
    }
    rs[tid] = sum; rq[tid] = sq;
    __syncthreads();
    {
        float4* outp = reinterpret_cast<float4*>(ybuf + ((size_t)(n * O + o)) * 6400);
        const float4* sp = reinterpret_cast<const float4*>(xs);
        for (int i = tid; i < 1600; i += 64) outp[i] = sp[i];
    }
    for (int st = 32; st > 0; st >>= 1) {
        if (tid < st) { rs[tid] += rs[tid + st]; rq[tid] += rq[tid + st]; }
        __syncthreads();
    }
    if (tid == 0) g_part2[o * NB + n] = make_float2(rs[0], rq[0]);
}

// ---------------- K4: BN stats combine ----------------
__global__ void k_stats2(const float* __restrict__ bnw, const float* __restrict__ bnb)
{
    int o = threadIdx.x;
    float s = 0.f, s2 = 0.f;
    for (int nn = 0; nn < NB; ++nn) {
        float2 p = g_part2[o * NB + nn];
        s += p.x; s2 += p.y;
    }
    float M = (float)(NB * T * V);
    float mean = s / M;
    float var  = s2 / M - mean * mean;
    float sc = bnw[o] * rsqrtf(var + 1e-5f);
    g_stats[o] = make_float2(sc, bnb[o] - mean * sc);
}

// ---------------- K5: BN apply + residual + relu ----------------
__global__ void k_final(float4* __restrict__ ybuf, const float4* __restrict__ x)
{
    int idx = blockIdx.x * 256 + threadIdx.x;
    int o = (idx / (T * V / 4)) & 63;
    float2 ss = g_stats[o];
    float4 y = ybuf[idx], xx = x[idx];
    y.x = fmaxf(fmaf(y.x, ss.x, ss.y) + xx.x, 0.f);
    y.y = fmaxf(fmaf(y.y, ss.x, ss.y) + xx.y, 0.f);
    y.z = fmaxf(fmaf(y.z, ss.x, ss.y) + xx.z, 0.f);
    y.w = fmaxf(fmaf(y.w, ss.x, ss.y) + xx.w, 0.f);
    ybuf[idx] = y;
}

// ---------------- launch ----------------
extern "C" void kernel_launch(void* const* d_in, const int* in_sizes, int n_in,
                              void* d_out, int out_size)
{
    (void)in_sizes; (void)n_in; (void)out_size;
    const float* x    = (const float*)d_in[0];
    const float* A    = (const float*)d_in[1];
    const float* alph = (const float*)d_in[2];
    const float* w1   = (const float*)d_in[3];
    const float* b1   = (const float*)d_in[4];
    const float* w2   = (const float*)d_in[5];
    const float* b2   = (const float*)d_in[6];
    const float* w3   = (const float*)d_in[7];
    const float* b3   = (const float*)d_in[8];
    const float* w4   = (const float*)d_in[9];
    const float* b4   = (const float*)d_in[10];
    const float* pw1  = (const float*)d_in[11];
    const float* pb1  = (const float*)d_in[12];
    const float* pw2  = (const float*)d_in[13];
    const float* pb2  = (const float*)d_in[14];
    const float* dww  = (const float*)d_in[15];
    const float* pjw  = (const float*)d_in[16];
    const float* beta = (const float*)d_in[17];
    const float* gamma= (const float*)d_in[18];
    const float* bnw  = (const float*)d_in[19];
    const float* bnb  = (const float*)d_in[20];
    float* out = (float*)d_out;

    cudaFuncSetAttribute(k_R,  cudaFuncAttributeMaxDynamicSharedMemorySize, 15800 * 4);
    cudaFuncSetAttribute(k_x3, cudaFuncAttributeMaxDynamicSharedMemorySize, KA_SMEM_B);
    cudaFuncSetAttribute(k_y,  cudaFuncAttributeMaxDynamicSharedMemorySize, KY_SMEM_B);

    k_xm<<<NB * C, 256>>>(x);
    k_w3d<<<S * C * O / 256, 256>>>(w3);
    k_R<<<dim3(NB, S), 256, 15800 * 4>>>(A, alph, w1, b1, w2, b2, w4, b4,
                                         pw1, pb1, pw2, pb2, dww, pjw, beta, gamma);
    k_x3<<<dim3(T * V / TVT, NB), 256, KA_SMEM_B>>>(x, b3);
    k_y<<<dim3(O, NB), 64, KY_SMEM_B>>>(out);
    k_stats2<<<1, O>>>(bnw, bnb);
    k_final<<<(NB * C * T * V) / 1024, 256>>>((float4*)out, (const float4*)x);
}

// round 11
// speedup vs baseline: 2.0544x; 1.0473x over previous
#include <cuda_runtime.h>
#include <cuda_bf16.h>

#define NB 64
#define C  64
#define T  256
#define V  25
#define S  3
#define R  8
#define O  64

typedef unsigned long long ull;
typedef unsigned int u32;

// ---------------- scratch ----------------
__device__ float  g_xm[NB * C * V];
__device__ __nv_bfloat16 g_xbh[(size_t)NB * C * T * V];  // x hi
__device__ __nv_bfloat16 g_xbl[(size_t)NB * C * T * V];  // x lo (residual)
__device__ __nv_bfloat16 g_w3h[S * O * C];               // w3 hi, rows [s*64+o][c]
__device__ __nv_bfloat16 g_w3l[S * O * C];               // w3 lo
__device__ float  g_R4[(size_t)S * NB * O * V * V];
__device__ float  g_x3[(size_t)S * NB * O * T * V];      // fp32
__device__ float2 g_stats[O];
__device__ float2 g_part2[O * NB];

// ---------------- f32x2 helpers (k_y) ----------------
__device__ __forceinline__ ull pk(float lo, float hi) {
    ull r; asm("mov.b64 %0, {%1,%2};" : "=l"(r) : "f"(lo), "f"(hi)); return r;
}
__device__ __forceinline__ void upk(float& lo, float& hi, ull v) {
    asm("mov.b64 {%0,%1}, %2;" : "=f"(lo), "=f"(hi) : "l"(v));
}
__device__ __forceinline__ ull f2fma(ull a, ull b, ull c) {
    ull d; asm("fma.rn.f32x2 %0, %1, %2, %3;" : "=l"(d) : "l"(a), "l"(b), "l"(c)); return d;
}

// ---------------- warp-MMA helpers (sm_80+ PTX) ----------------
__device__ __forceinline__ u32 s2u(const void* p) {
    u32 a; asm("{ .reg .u64 t; cvta.to.shared.u64 t, %1; cvt.u32.u64 %0, t; }" : "=r"(a) : "l"(p));
    return a;
}
__device__ __forceinline__ u32 sw128(u32 b) { return b ^ ((b >> 3) & 0x70); }

__device__ __forceinline__ void ldsm_x4(u32* r, u32 addr) {
    asm volatile("ldmatrix.sync.aligned.m8n8.x4.shared.b16 {%0,%1,%2,%3}, [%4];"
        : "=r"(r[0]), "=r"(r[1]), "=r"(r[2]), "=r"(r[3]) : "r"(addr));
}
__device__ __forceinline__ void ldsm_x4_t(u32* r, u32 addr) {
    asm volatile("ldmatrix.sync.aligned.m8n8.x4.trans.shared.b16 {%0,%1,%2,%3}, [%4];"
        : "=r"(r[0]), "=r"(r[1]), "=r"(r[2]), "=r"(r[3]) : "r"(addr));
}
__device__ __forceinline__ void mma16816(float* d, const u32* a, u32 b0, u32 b1) {
    asm volatile(
        "mma.sync.aligned.m16n8k16.row.col.f32.bf16.bf16.f32 "
        "{%0,%1,%2,%3}, {%4,%5,%6,%7}, {%8,%9}, {%0,%1,%2,%3};"
        : "+f"(d[0]), "+f"(d[1]), "+f"(d[2]), "+f"(d[3])
        : "r"(a[0]), "r"(a[1]), "r"(a[2]), "r"(a[3]), "r"(b0), "r"(b1));
}

// ---------------- K0a: x -> bf16 hi/lo ----------------
__global__ void k_xbf(const float4* __restrict__ x) {
    size_t i = (size_t)blockIdx.x * 256 + threadIdx.x;
    float4 v = x[i];
    __nv_bfloat16 h0 = __float2bfloat16(v.x), h1 = __float2bfloat16(v.y);
    __nv_bfloat16 h2 = __float2bfloat16(v.z), h3 = __float2bfloat16(v.w);
    __nv_bfloat16 l0 = __float2bfloat16(v.x - __bfloat162float(h0));
    __nv_bfloat16 l1 = __float2bfloat16(v.y - __bfloat162float(h1));
    __nv_bfloat16 l2 = __float2bfloat16(v.z - __bfloat162float(h2));
    __nv_bfloat16 l3 = __float2bfloat16(v.w - __bfloat162float(h3));
    __nv_bfloat162* dh = reinterpret_cast<__nv_bfloat162*>(g_xbh);
    __nv_bfloat162* dl = reinterpret_cast<__nv_bfloat162*>(g_xbl);
    dh[2 * i]     = __nv_bfloat162(h0, h1);
    dh[2 * i + 1] = __nv_bfloat162(h2, h3);
    dl[2 * i]     = __nv_bfloat162(l0, l1);
    dl[2 * i + 1] = __nv_bfloat162(l2, l3);
}

// ---------------- K0b: w3 -> bf16 hi/lo (layout already [s][o][c]) ----------------
__global__ void k_wb(const float* __restrict__ w3g) {
    int i = blockIdx.x * 256 + threadIdx.x;
    float w = w3g[i];
    __nv_bfloat16 h = __float2bfloat16(w);
    g_w3h[i] = h;
    g_w3l[i] = __float2bfloat16(w - __bfloat162float(h));
}

// ---------------- K1: xm[n,c,v] = mean_t x ----------------
__global__ void k_xm(const float* __restrict__ x) {
    __shared__ float red[256 * V];
    int bx  = blockIdx.x;
    int tid = threadIdx.x;
    const float* row = x + (size_t)bx * T * V + (size_t)tid * V;
    #pragma unroll
    for (int v = 0; v < V; ++v) red[tid * V + v] = row[v];
    __syncthreads();
    for (int st = 128; st > 0; st >>= 1) {
        if (tid < st) {
            #pragma unroll
            for (int v = 0; v < V; ++v) red[tid * V + v] += red[(tid + st) * V + v];
        }
        __syncthreads();
    }
    if (tid < V) g_xm[bx * V + tid] = red[tid] * (1.0f / T);
}

// ---------------- K2: x3 GEMM via warp MMA, split-bf16 3-term fp32 emulation ----------------
constexpr int SM_AH = 0;        // 24576
constexpr int SM_AL = 24576;    // 24576
constexpr int SM_BH = 49152;    // 8192
constexpr int SM_BL = 57344;    // 8192
constexpr int SM_TOT = 65536;

__global__ void __launch_bounds__(384) k_x3m(const float* __restrict__ b3g)
{
    extern __shared__ char smc[];
    int tid = threadIdx.x, wid = tid >> 5, lane = tid & 31;
    int n = blockIdx.y, tv0 = blockIdx.x * 64;

    // A tiles (w3 hi/lo), swizzled: 192 rows x 128B each
    for (int i = tid; i < 2 * 192 * 8; i += 384) {
        int half = i >= 1536;
        int j = half ? (i - 1536) : i;
        int row = j >> 3, off = (j & 7) * 16;
        const char* src = reinterpret_cast<const char*>(half ? g_w3l : g_w3h);
        uint4 v = *reinterpret_cast<const uint4*>(src + row * 128 + off);
        *reinterpret_cast<uint4*>(smc + (half ? SM_AL : SM_AH) + sw128(row * 128 + off)) = v;
    }
    // B tiles (x hi/lo), swizzled: 64 rows x 128B each
    for (int i = tid; i < 2 * 64 * 8; i += 384) {
        int half = i >= 512;
        int j = half ? (i - 512) : i;
        int row = j >> 3, off = (j & 7) * 16;
        const char* src = reinterpret_cast<const char*>(half ? g_xbl : g_xbh);
        uint4 v = *reinterpret_cast<const uint4*>(
            src + ((size_t)(n * C + row) * 6400 + tv0) * 2 + off);
        *reinterpret_cast<uint4*>(smc + (half ? SM_BL : SM_BH) + sw128(row * 128 + off)) = v;
    }
    __syncthreads();

    u32 sah = s2u(smc + SM_AH), sal = s2u(smc + SM_AL);
    u32 sbh = s2u(smc + SM_BH), sbl = s2u(smc + SM_BL);
    int gid = lane >> 2, tig = lane & 3;
    int m0 = wid * 16;

    float acc[8][4];
    #pragma unroll
    for (int j = 0; j < 8; ++j)
        #pragma unroll
        for (int q = 0; q < 4; ++q) acc[j][q] = 0.f;

    // 3 terms: (A_hi,B_hi), (A_hi,B_lo), (A_lo,B_hi)
    #pragma unroll 1
    for (int p = 0; p < 3; ++p) {
        u32 saa = (p == 2) ? sal : sah;
        u32 sbb = (p == 1) ? sbl : sbh;
        #pragma unroll
        for (int k0 = 0; k0 < 64; k0 += 16) {
            u32 a[4];
            ldsm_x4(a, saa + sw128((m0 + (lane & 15)) * 128 + (lane >> 4) * 16 + k0 * 2));
            int krow = k0 + (lane & 7) + ((lane >> 3) & 1) * 8;
            #pragma unroll
            for (int nt = 0; nt < 4; ++nt) {
                u32 b[4];
                ldsm_x4_t(b, sbb + sw128(krow * 128 + nt * 32 + (lane >> 4) * 16));
                mma16816(acc[2 * nt],     a, b[0], b[1]);
                mma16816(acc[2 * nt + 1], a, b[2], b[3]);
            }
        }
    }

    // bias + store (D rows m = s*64 + o)
    int s = wid >> 2;
    int o0 = (wid & 3) * 16 + gid;
    float bias0 = b3g[s * O + o0];
    float bias1 = b3g[s * O + o0 + 8];
    float* d0 = g_x3 + (((size_t)s * NB + n) * O + o0) * 6400 + tv0;
    float* d1 = d0 + (size_t)8 * 6400;
    #pragma unroll
    for (int j = 0; j < 8; ++j) {
        int col = j * 8 + 2 * tig;
        *reinterpret_cast<float2*>(d0 + col) =
            make_float2(acc[j][0] + bias0, acc[j][1] + bias0);
        *reinterpret_cast<float2*>(d1 + col) =
            make_float2(acc[j][2] + bias1, acc[j][3] + bias1);
    }
}

// ---------------- K3: build scalar R4 ----------------
__global__ void k_R(const float* __restrict__ Ag,   const float* __restrict__ alphag,
                    const float* __restrict__ w1g,  const float* __restrict__ b1g,
                    const float* __restrict__ w2g,  const float* __restrict__ b2g,
                    const float* __restrict__ w4g,  const float* __restrict__ b4g,
                    const float* __restrict__ pw1g, const float* __restrict__ pb1g,
                    const float* __restrict__ pw2g, const float* __restrict__ pb2g,
                    const float* __restrict__ dwwg, const float* __restrict__ pjwg,
                    const float* __restrict__ betag,const float* __restrict__ gammag)
{
    extern __shared__ float sm[];
    float* q1s = sm;            // 5000 (reused as ta)
    float* qas = sm + 5000;     // 5000
    float* ds  = sm + 10000;    // 5000
    float* x1s = sm + 15000;    // 200
    float* x2s = sm + 15200;    // 200
    float* as_ = sm + 15400;    // 200
    float* bs_ = sm + 15600;    // 200

    int n = blockIdx.x, s = blockIdx.y;
    int tid = threadIdx.x;
    const float* xm = g_xm + n * (C * V);

    for (int idx = tid; idx < R * V; idx += blockDim.x) {
        int r = idx / V, u = idx % V;
        float s1 = b1g[s * R + r], s2 = b2g[s * R + r];
        const float* w1r = w1g + (s * R + r) * C;
        const float* w2r = w2g + (s * R + r) * C;
        for (int c = 0; c < C; ++c) {
            float xv = xm[c * V + u];
            s1 = fmaf(w1r[c], xv, s1);
            s2 = fmaf(w2r[c], xv, s2);
        }
        x1s[idx] = s1; x2s[idx] = s2;
    }
    __syncthreads();
    for (int idx = tid; idx < R * V; idx += blockDim.x) {
        int r = idx / V, u = idx % V;
        const float* p1 = pw1g + (s * R + r) * (2 * R);
        float av = 0.f, bv = 0.f;
        #pragma unroll
        for (int p = 0; p < R; ++p) {
            av = fmaf(p1[p],     x2s[p * V + u], av);
            bv = fmaf(p1[R + p], x2s[p * V + u], bv);
        }
        as_[idx] = av; bs_[idx] = bv;
    }
    __syncthreads();
    for (int idx = tid; idx < R * V * V; idx += blockDim.x) {
        int r = idx / (V * V), uv = idx % (V * V), u = uv / V, v = uv % V;
        q1s[idx] = tanhf(x1s[r * V + u] - x2s[r * V + v]);
    }
    __syncthreads();
    float gma = gammag[s];
    for (int uv = tid; uv < V * V; uv += blockDim.x) {
        int u = uv / V, v = uv % V;
        float h[R];
        #pragma unroll
        for (int p = 0; p < R; ++p)
            h[p] = fmaxf(as_[p * V + u] + bs_[p * V + v] + pb1g[s * R + p], 0.f);
        #pragma unroll
        for (int r = 0; r < R; ++r) {
            float q2 = pb2g[s * R + r];
            const float* p2 = pw2g + (s * R + r) * R;
            #pragma unroll
            for (int p = 0; p < R; ++p) q2 = fmaf(p2[p], h[p], q2);
            qas[r * V * V + uv] = q1s[r * V * V + uv] + gma * q2;
        }
    }
    __syncthreads();
    for (int idx = tid; idx < R * V * V; idx += blockDim.x) {
        int r = idx / (V * V), uv = idx % (V * V), u = uv / V, v = uv % V;
        const float* kw = dwwg + (s * R + r) * 9;
        float acc = 0.f;
        #pragma unroll
        for (int ki = 0; ki < 3; ++ki) {
            int uu = u + ki - 1; if (uu < 0 || uu >= V) continue;
            #pragma unroll
            for (int kj = 0; kj < 3; ++kj) {
                int vv = v + kj - 1; if (vv < 0 || vv >= V) continue;
                acc = fmaf(q1s[r * V * V + uu * V + vv], kw[ki * 3 + kj], acc);
            }
        }
        ds[idx] = acc;
    }
    __syncthreads();
    for (int idx = tid; idx < R * V * V; idx += blockDim.x) {
        int r = idx / (V * V), uv = idx % (V * V), u = uv / V, v = uv % V;
        float acc = 0.f;
        for (int ki = -1; ki <= 1; ++ki) {
            int uu = u + ki; if (uu < 0 || uu >= V) continue;
            for (int kj = -1; kj <= 1; ++kj) {
                int vv = v + kj; if (vv < 0 || vv >= V) continue;
                acc += ds[r * V * V + uu * V + vv];
            }
        }
        q1s[idx] = tanhf(acc * (1.f / 9.f));
    }
    __syncthreads();
    float alpha = alphag[0], beta = betag[s];
    const float* ta = q1s;
    float* dst = g_R4 + ((size_t)(s * NB + n)) * O * 625;
    for (int idx = tid; idx < O * 625; idx += blockDim.x) {
        int o = idx / 625, uv = idx % 625;
        float a1 = b4g[s * O + o], a2 = 0.f;
        const float* w4r = w4g + (s * O + o) * R;
        const float* pjr = pjwg + (s * O + o) * R;
        #pragma unroll
        for (int r = 0; r < R; ++r) {
            a1 = fmaf(w4r[r], qas[r * V * V + uv], a1);
            a2 = fmaf(pjr[r], ta[r * V * V + uv], a2);
        }
        dst[idx] = fmaf(alpha, a1, Ag[s * V * V + uv]) + beta * a2;
    }
}

// ---------------- K4: y = R-contraction, 4t/thread, fused BN partials ----------------
constexpr int KY_SMEM_B = (6400 + 1875 + 128) * 4;

__global__ void __launch_bounds__(64) k_y(float* __restrict__ ybuf)
{
    extern __shared__ float smf[];
    float* xs = smf;            // 6400
    float* Rs = smf + 6400;     // 1875
    float* rs = smf + 8275;     // 64
    float* rq = smf + 8339;     // 64
    int n = blockIdx.y, o = blockIdx.x;
    int tid = threadIdx.x;

    for (int i = tid; i < S * 625; i += 64) {
        int s = i / 625, r = i % 625;
        Rs[i] = g_R4[(((size_t)s * NB + n) * O + o) * 625 + r];
    }

    ull acc[25][2];
    #pragma unroll
    for (int u = 0; u < 25; ++u) { acc[u][0] = 0ull; acc[u][1] = 0ull; }

    #pragma unroll 1
    for (int s = 0; s < S; ++s) {
        __syncthreads();
        {
            const float4* src = reinterpret_cast<const float4*>(
                g_x3 + (((size_t)(s * NB + n)) * O + o) * 6400);
            float4* dst = reinterpret_cast<float4*>(xs);
            for (int i = tid; i < 1600; i += 64) dst[i] = src[i];
        }
        __syncthreads();
        const float* Rp = Rs + s * 625;
        #pragma unroll 1
        for (int v = 0; v < 25; ++v) {
            float a0 = xs[tid * 25 + v];
            float a1 = xs[(tid + 64) * 25 + v];
            float a2 = xs[(tid + 128) * 25 + v];
            float a3 = xs[(tid + 192) * 25 + v];
            ull x0 = pk(a0, a1), x1 = pk(a2, a3);
            #pragma unroll
            for (int u = 0; u < 25; ++u) {
                float rv = Rp[u * 25 + v];
                ull rd = pk(rv, rv);
                acc[u][0] = f2fma(x0, rd, acc[u][0]);
                acc[u][1] = f2fma(x1, rd, acc[u][1]);
            }
        }
    }

    float sum = 0.f, sq = 0.f;
    __syncthreads();
    #pragma unroll
    for (int u = 0; u < 25; ++u) {
        float z0, z1, z2, z3;
        upk(z0, z1, acc[u][0]);
        upk(z2, z3, acc[u][1]);
        xs[tid * 25 + u]         = z0;
        xs[(tid + 64) * 25 + u]  = z1;
        xs[(tid + 128) * 25 + u] = z2;
        xs[(tid + 192) * 25 + u] = z3;
        sum += z0 + z1 + z2 + z3;
        sq  = fmaf(z0, z0, sq); sq = fmaf(z1, z1, sq);
        sq  = fmaf(z2, z2, sq); sq = fmaf(z3, z3, sq);
    }
    rs[tid] = sum; rq[tid] = sq;
    __syncthreads();
    {
        float4* outp = reinterpret_cast<float4*>(ybuf + ((size_t)(n * O + o)) * 6400);
        const float4* sp = reinterpret_cast<const float4*>(xs);
        for (int i = tid; i < 1600; i += 64) outp[i] = sp[i];
    }
    for (int st = 32; st > 0; st >>= 1) {
        if (tid < st) { rs[tid] += rs[tid + st]; rq[tid] += rq[tid + st]; }
        __syncthreads();
    }
    if (tid == 0) g_part2[o * NB + n] = make_float2(rs[0], rq[0]);
}

// ---------------- K5: BN stats combine ----------------
__global__ void k_stats2(const float* __restrict__ bnw, const float* __restrict__ bnb)
{
    int o = threadIdx.x;
    float s = 0.f, s2 = 0.f;
    for (int nn = 0; nn < NB; ++nn) {
        float2 p = g_part2[o * NB + nn];
        s += p.x; s2 += p.y;
    }
    float M = (float)(NB * T * V);
    float mean = s / M;
    float var  = s2 / M - mean * mean;
    float sc = bnw[o] * rsqrtf(var + 1e-5f);
    g_stats[o] = make_float2(sc, bnb[o] - mean * sc);
}

// ---------------- K6: BN apply + residual + relu ----------------
__global__ void k_final(float4* __restrict__ ybuf, const float4* __restrict__ x)
{
    int idx = blockIdx.x * 256 + threadIdx.x;
    int o = (idx / (T * V / 4)) & 63;
    float2 ss = g_stats[o];
    float4 y = ybuf[idx], xx = x[idx];
    y.x = fmaxf(fmaf(y.x, ss.x, ss.y) + xx.x, 0.f);
    y.y = fmaxf(fmaf(y.y, ss.x, ss.y) + xx.y, 0.f);
    y.z = fmaxf(fmaf(y.z, ss.x, ss.y) + xx.z, 0.f);
    y.w = fmaxf(fmaf(y.w, ss.x, ss.y) + xx.w, 0.f);
    ybuf[idx] = y;
}

// ---------------- launch ----------------
extern "C" void kernel_launch(void* const* d_in, const int* in_sizes, int n_in,
                              void* d_out, int out_size)
{
    (void)in_sizes; (void)n_in; (void)out_size;
    const float* x    = (const float*)d_in[0];
    const float* A    = (const float*)d_in[1];
    const float* alph = (const float*)d_in[2];
    const float* w1   = (const float*)d_in[3];
    const float* b1   = (const float*)d_in[4];
    const float* w2   = (const float*)d_in[5];
    const float* b2   = (const float*)d_in[6];
    const float* w3   = (const float*)d_in[7];
    const float* b3   = (const float*)d_in[8];
    const float* w4   = (const float*)d_in[9];
    const float* b4   = (const float*)d_in[10];
    const float* pw1  = (const float*)d_in[11];
    const float* pb1  = (const float*)d_in[12];
    const float* pw2  = (const float*)d_in[13];
    const float* pb2  = (const float*)d_in[14];
    const float* dww  = (const float*)d_in[15];
    const float* pjw  = (const float*)d_in[16];
    const float* beta = (const float*)d_in[17];
    const float* gamma= (const float*)d_in[18];
    const float* bnw  = (const float*)d_in[19];
    const float* bnb  = (const float*)d_in[20];
    float* out = (float*)d_out;

    cudaFuncSetAttribute(k_R,   cudaFuncAttributeMaxDynamicSharedMemorySize, 15800 * 4);
    cudaFuncSetAttribute(k_x3m, cudaFuncAttributeMaxDynamicSharedMemorySize, SM_TOT);
    cudaFuncSetAttribute(k_y,   cudaFuncAttributeMaxDynamicSharedMemorySize, KY_SMEM_B);

    k_xbf<<<(NB * C * T * V) / 1024, 256>>>((const float4*)x);
    k_wb<<<S * O * C / 256, 256>>>(w3);
    k_xm<<<NB * C, 256>>>(x);
    k_x3m<<<dim3(100, NB), 384, SM_TOT>>>(b3);
    k_R<<<dim3(NB, S), 512, 15800 * 4>>>(A, alph, w1, b1, w2, b2, w4, b4,
                                         pw1, pb1, pw2, pb2, dww, pjw, beta, gamma);
    k_y<<<dim3(O, NB), 64, KY_SMEM_B>>>(out);
    k_stats2<<<1, O>>>(bnw, bnb);
    k_final<<<(NB * C * T * V) / 1024, 256>>>((float4*)out, (const float4*)x);
}

// round 12
// speedup vs baseline: 2.2868x; 1.1131x over previous
#include <cuda_runtime.h>
#include <cuda_bf16.h>

#define NB 64
#define C  64
#define T  256
#define V  25
#define S  3
#define R  8
#define O  64

typedef unsigned long long ull;
typedef unsigned int u32;

// ---------------- scratch ----------------
__device__ float  g_xm[NB * C * V];
__device__ __nv_bfloat16 g_w3h[S * O * C];               // w3 hi, rows [s*64+o][c]
__device__ __nv_bfloat16 g_w3l[S * O * C];               // w3 lo
__device__ float  g_R4[(size_t)S * NB * O * V * V];
__device__ float  g_x3[(size_t)S * NB * O * T * V];      // fp32
__device__ float2 g_stats[O];
__device__ float2 g_part2[O * NB];

// ---------------- f32x2 helpers (k_y) ----------------
__device__ __forceinline__ ull pk(float lo, float hi) {
    ull r; asm("mov.b64 %0, {%1,%2};" : "=l"(r) : "f"(lo), "f"(hi)); return r;
}
__device__ __forceinline__ void upk(float& lo, float& hi, ull v) {
    asm("mov.b64 {%0,%1}, %2;" : "=f"(lo), "=f"(hi) : "l"(v));
}
__device__ __forceinline__ ull f2fma(ull a, ull b, ull c) {
    ull d; asm("fma.rn.f32x2 %0, %1, %2, %3;" : "=l"(d) : "l"(a), "l"(b), "l"(c)); return d;
}

// ---------------- warp-MMA helpers (sm_80+ PTX) ----------------
__device__ __forceinline__ u32 s2u(const void* p) {
    u32 a; asm("{ .reg .u64 t; cvta.to.shared.u64 t, %1; cvt.u32.u64 %0, t; }" : "=r"(a) : "l"(p));
    return a;
}
__device__ __forceinline__ u32 sw128(u32 b) { return b ^ ((b >> 3) & 0x70); }

__device__ __forceinline__ void ldsm_x4(u32* r, u32 addr) {
    asm volatile("ldmatrix.sync.aligned.m8n8.x4.shared.b16 {%0,%1,%2,%3}, [%4];"
        : "=r"(r[0]), "=r"(r[1]), "=r"(r[2]), "=r"(r[3]) : "r"(addr));
}
__device__ __forceinline__ void ldsm_x4_t(u32* r, u32 addr) {
    asm volatile("ldmatrix.sync.aligned.m8n8.x4.trans.shared.b16 {%0,%1,%2,%3}, [%4];"
        : "=r"(r[0]), "=r"(r[1]), "=r"(r[2]), "=r"(r[3]) : "r"(addr));
}
__device__ __forceinline__ void mma16816(float* d, const u32* a, u32 b0, u32 b1) {
    asm volatile(
        "mma.sync.aligned.m16n8k16.row.col.f32.bf16.bf16.f32 "
        "{%0,%1,%2,%3}, {%4,%5,%6,%7}, {%8,%9}, {%0,%1,%2,%3};"
        : "+f"(d[0]), "+f"(d[1]), "+f"(d[2]), "+f"(d[3])
        : "r"(a[0]), "r"(a[1]), "r"(a[2]), "r"(a[3]), "r"(b0), "r"(b1));
}

// ---------------- K0: w3 -> bf16 hi/lo (layout already [s][o][c]) ----------------
__global__ void k_wb(const float* __restrict__ w3g) {
    int i = blockIdx.x * 256 + threadIdx.x;
    float w = w3g[i];
    __nv_bfloat16 h = __float2bfloat16(w);
    g_w3h[i] = h;
    g_w3l[i] = __float2bfloat16(w - __bfloat162float(h));
}

// ---------------- K1: xm[n,c,v] = mean_t x ----------------
__global__ void k_xm(const float* __restrict__ x) {
    __shared__ float red[256 * V];
    int bx  = blockIdx.x;
    int tid = threadIdx.x;
    const float* row = x + (size_t)bx * T * V + (size_t)tid * V;
    #pragma unroll
    for (int v = 0; v < V; ++v) red[tid * V + v] = row[v];
    __syncthreads();
    for (int st = 128; st > 0; st >>= 1) {
        if (tid < st) {
            #pragma unroll
            for (int v = 0; v < V; ++v) red[tid * V + v] += red[(tid + st) * V + v];
        }
        __syncthreads();
    }
    if (tid < V) g_xm[bx * V + tid] = red[tid] * (1.0f / T);
}

// ---------------- K2: x3 GEMM, split-bf16 3-term, fused x conversion ----------------
constexpr int SM_AH = 0;        // 24576
constexpr int SM_AL = 24576;    // 24576
constexpr int SM_BH = 49152;    // 8192
constexpr int SM_BL = 57344;    // 8192
constexpr int SM_TOT = 65536;

__global__ void __launch_bounds__(384) k_x3m(const float* __restrict__ x,
                                             const float* __restrict__ b3g)
{
    extern __shared__ char smc[];
    int tid = threadIdx.x, wid = tid >> 5, lane = tid & 31;
    int n = blockIdx.y, tv0 = blockIdx.x * 64;

    // A tiles (w3 hi/lo bf16), swizzled: 192 rows x 128B each
    for (int i = tid; i < 2 * 192 * 8; i += 384) {
        int half = i >= 1536;
        int j = half ? (i - 1536) : i;
        int row = j >> 3, off = (j & 7) * 16;
        const char* src = reinterpret_cast<const char*>(half ? g_w3l : g_w3h);
        uint4 v = *reinterpret_cast<const uint4*>(src + row * 128 + off);
        *reinterpret_cast<uint4*>(smc + (half ? SM_AL : SM_AH) + sw128(row * 128 + off)) = v;
    }
    // B tiles: read x fp32, convert to hi/lo bf16 in-flight (k_xbf folded in)
    for (int i = tid; i < 64 * 32; i += 384) {
        int c = i >> 5, j2 = i & 31;    // j2 indexes a float2 pair
        float2 v = *reinterpret_cast<const float2*>(
            x + ((size_t)(n * C + c)) * 6400 + tv0 + j2 * 2);
        __nv_bfloat16 h0 = __float2bfloat16(v.x), h1 = __float2bfloat16(v.y);
        __nv_bfloat16 l0 = __float2bfloat16(v.x - __bfloat162float(h0));
        __nv_bfloat16 l1 = __float2bfloat16(v.y - __bfloat162float(h1));
        u32 off = sw128((u32)(c * 128 + j2 * 4));
        *reinterpret_cast<__nv_bfloat162*>(smc + SM_BH + off) = __nv_bfloat162(h0, h1);
        *reinterpret_cast<__nv_bfloat162*>(smc + SM_BL + off) = __nv_bfloat162(l0, l1);
    }
    __syncthreads();

    u32 sah = s2u(smc + SM_AH), sal = s2u(smc + SM_AL);
    u32 sbh = s2u(smc + SM_BH), sbl = s2u(smc + SM_BL);
    int gid = lane >> 2, tig = lane & 3;
    int m0 = wid * 16;

    float acc[8][4];
    #pragma unroll
    for (int j = 0; j < 8; ++j)
        #pragma unroll
        for (int q = 0; q < 4; ++q) acc[j][q] = 0.f;

    #pragma unroll
    for (int k0 = 0; k0 < 64; k0 += 16) {
        u32 arow = sw128((m0 + (lane & 15)) * 128 + (lane >> 4) * 16 + k0 * 2);
        u32 ah[4], al[4];
        ldsm_x4(ah, sah + arow);
        ldsm_x4(al, sal + arow);
        int krow = k0 + (lane & 7) + ((lane >> 3) & 1) * 8;
        u32 bh[4][4], bl[4][4];
        #pragma unroll
        for (int nt = 0; nt < 4; ++nt) {
            u32 boff = sw128(krow * 128 + nt * 32 + (lane >> 4) * 16);
            ldsm_x4_t(bh[nt], sbh + boff);
            ldsm_x4_t(bl[nt], sbl + boff);
        }
        #pragma unroll
        for (int nt = 0; nt < 4; ++nt) {
            mma16816(acc[2 * nt],     ah, bh[nt][0], bh[nt][1]);
            mma16816(acc[2 * nt + 1], ah, bh[nt][2], bh[nt][3]);
            mma16816(acc[2 * nt],     ah, bl[nt][0], bl[nt][1]);
            mma16816(acc[2 * nt + 1], ah, bl[nt][2], bl[nt][3]);
            mma16816(acc[2 * nt],     al, bh[nt][0], bh[nt][1]);
            mma16816(acc[2 * nt + 1], al, bh[nt][2], bh[nt][3]);
        }
    }

    // bias + store (D rows m = s*64 + o)
    int s = wid >> 2;
    int o0 = (wid & 3) * 16 + gid;
    float bias0 = b3g[s * O + o0];
    float bias1 = b3g[s * O + o0 + 8];
    float* d0 = g_x3 + (((size_t)s * NB + n) * O + o0) * 6400 + tv0;
    float* d1 = d0 + (size_t)8 * 6400;
    #pragma unroll
    for (int j = 0; j < 8; ++j) {
        int col = j * 8 + 2 * tig;
        *reinterpret_cast<float2*>(d0 + col) =
            make_float2(acc[j][0] + bias0, acc[j][1] + bias0);
        *reinterpret_cast<float2*>(d1 + col) =
            make_float2(acc[j][2] + bias1, acc[j][3] + bias1);
    }
}

// ---------------- K3: build scalar R4 ----------------
__global__ void k_R(const float* __restrict__ Ag,   const float* __restrict__ alphag,
                    const float* __restrict__ w1g,  const float* __restrict__ b1g,
                    const float* __restrict__ w2g,  const float* __restrict__ b2g,
                    const float* __restrict__ w4g,  const float* __restrict__ b4g,
                    const float* __restrict__ pw1g, const float* __restrict__ pb1g,
                    const float* __restrict__ pw2g, const float* __restrict__ pb2g,
                    const float* __restrict__ dwwg, const float* __restrict__ pjwg,
                    const float* __restrict__ betag,const float* __restrict__ gammag)
{
    extern __shared__ float sm[];
    float* q1s = sm;            // 5000 (reused as ta)
    float* qas = sm + 5000;     // 5000
    float* ds  = sm + 10000;    // 5000
    float* x1s = sm + 15000;    // 200
    float* x2s = sm + 15200;    // 200
    float* as_ = sm + 15400;    // 200
    float* bs_ = sm + 15600;    // 200

    int n = blockIdx.x, s = blockIdx.y;
    int tid = threadIdx.x;
    const float* xm = g_xm + n * (C * V);

    for (int idx = tid; idx < R * V; idx += blockDim.x) {
        int r = idx / V, u = idx % V;
        float s1 = b1g[s * R + r], s2 = b2g[s * R + r];
        const float* w1r = w1g + (s * R + r) * C;
        const float* w2r = w2g + (s * R + r) * C;
        for (int c = 0; c < C; ++c) {
            float xv = xm[c * V + u];
            s1 = fmaf(w1r[c], xv, s1);
            s2 = fmaf(w2r[c], xv, s2);
        }
        x1s[idx] = s1; x2s[idx] = s2;
    }
    __syncthreads();
    for (int idx = tid; idx < R * V; idx += blockDim.x) {
        int r = idx / V, u = idx % V;
        const float* p1 = pw1g + (s * R + r) * (2 * R);
        float av = 0.f, bv = 0.f;
        #pragma unroll
        for (int p = 0; p < R; ++p) {
            av = fmaf(p1[p],     x2s[p * V + u], av);
            bv = fmaf(p1[R + p], x2s[p * V + u], bv);
        }
        as_[idx] = av; bs_[idx] = bv;
    }
    __syncthreads();
    for (int idx = tid; idx < R * V * V; idx += blockDim.x) {
        int r = idx / (V * V), uv = idx % (V * V), u = uv / V, v = uv % V;
        q1s[idx] = tanhf(x1s[r * V + u] - x2s[r * V + v]);
    }
    __syncthreads();
    float gma = gammag[s];
    for (int uv = tid; uv < V * V; uv += blockDim.x) {
        int u = uv / V, v = uv % V;
        float h[R];
        #pragma unroll
        for (int p = 0; p < R; ++p)
            h[p] = fmaxf(as_[p * V + u] + bs_[p * V + v] + pb1g[s * R + p], 0.f);
        #pragma unroll
        for (int r = 0; r < R; ++r) {
            float q2 = pb2g[s * R + r];
            const float* p2 = pw2g + (s * R + r) * R;
            #pragma unroll
            for (int p = 0; p < R; ++p) q2 = fmaf(p2[p], h[p], q2);
            qas[r * V * V + uv] = q1s[r * V * V + uv] + gma * q2;
        }
    }
    __syncthreads();
    for (int idx = tid; idx < R * V * V; idx += blockDim.x) {
        int r = idx / (V * V), uv = idx % (V * V), u = uv / V, v = uv % V;
        const float* kw = dwwg + (s * R + r) * 9;
        float acc = 0.f;
        #pragma unroll
        for (int ki = 0; ki < 3; ++ki) {
            int uu = u + ki - 1; if (uu < 0 || uu >= V) continue;
            #pragma unroll
            for (int kj = 0; kj < 3; ++kj) {
                int vv = v + kj - 1; if (vv < 0 || vv >= V) continue;
                acc = fmaf(q1s[r * V * V + uu * V + vv], kw[ki * 3 + kj], acc);
            }
        }
        ds[idx] = acc;
    }
    __syncthreads();
    for (int idx = tid; idx < R * V * V; idx += blockDim.x) {
        int r = idx / (V * V), uv = idx % (V * V), u = uv / V, v = uv % V;
        float acc = 0.f;
        for (int ki = -1; ki <= 1; ++ki) {
            int uu = u + ki; if (uu < 0 || uu >= V) continue;
            for (int kj = -1; kj <= 1; ++kj) {
                int vv = v + kj; if (vv < 0 || vv >= V) continue;
                acc += ds[r * V * V + uu * V + vv];
            }
        }
        q1s[idx] = tanhf(acc * (1.f / 9.f));
    }
    __syncthreads();
    float alpha = alphag[0], beta = betag[s];
    const float* ta = q1s;
    float* dst = g_R4 + ((size_t)(s * NB + n)) * O * 625;
    for (int idx = tid; idx < O * 625; idx += blockDim.x) {
        int o = idx / 625, uv = idx % 625;
        float a1 = b4g[s * O + o], a2 = 0.f;
        const float* w4r = w4g + (s * O + o) * R;
        const float* pjr = pjwg + (s * O + o) * R;
        #pragma unroll
        for (int r = 0; r < R; ++r) {
            a1 = fmaf(w4r[r], qas[r * V * V + uv], a1);
            a2 = fmaf(pjr[r], ta[r * V * V + uv], a2);
        }
        dst[idx] = fmaf(alpha, a1, Ag[s * V * V + uv]) + beta * a2;
    }
}

// ---------------- K4: y = R-contraction, 4t/thread, float4 R, fused BN partials ----------------
// smem: xs 6400 | Rs4 2100 (3 x 25 x 28, padded) | rs 64 | rq 64
constexpr int KY_SMEM_B = (6400 + 2100 + 128) * 4;     // 34512

__global__ void __launch_bounds__(64) k_y(float* __restrict__ ybuf)
{
    extern __shared__ float smf[];
    float* xs  = smf;            // 6400
    float* Rs4 = smf + 6400;     // 2100
    float* rs  = smf + 8500;     // 64
    float* rq  = smf + 8564;     // 64
    int n = blockIdx.y, o = blockIdx.x;
    int tid = threadIdx.x;

    // stage R padded to 28 per u-row (zeros beyond v=24)
    for (int i = tid; i < S * 25 * 28; i += 64) {
        int s = i / 700, rem = i % 700, u = rem / 28, j = rem % 28;
        Rs4[i] = (j < 25) ? g_R4[(((size_t)s * NB + n) * O + o) * 625 + u * 25 + j] : 0.f;
    }

    ull acc[25][2];
    #pragma unroll
    for (int u = 0; u < 25; ++u) { acc[u][0] = 0ull; acc[u][1] = 0ull; }

    #pragma unroll 1
    for (int s = 0; s < S; ++s) {
        __syncthreads();
        {
            const float4* src = reinterpret_cast<const float4*>(
                g_x3 + (((size_t)(s * NB + n)) * O + o) * 6400);
            float4* dst = reinterpret_cast<float4*>(xs);
            for (int i = tid; i < 1600; i += 64) dst[i] = src[i];
        }
        __syncthreads();
        const float* Rp = Rs4 + s * 700;
        // v groups of 4 (vg 0..5), R via float4 broadcast
        #pragma unroll 1
        for (int vg = 0; vg < 6; ++vg) {
            ull xq[4][2];
            #pragma unroll
            for (int vv = 0; vv < 4; ++vv) {
                int v = vg * 4 + vv;
                float a0 = xs[tid * 25 + v];
                float a1 = xs[(tid + 64) * 25 + v];
                float a2 = xs[(tid + 128) * 25 + v];
                float a3 = xs[(tid + 192) * 25 + v];
                xq[vv][0] = pk(a0, a1); xq[vv][1] = pk(a2, a3);
            }
            #pragma unroll
            for (int u = 0; u < 25; ++u) {
                float4 rf = *reinterpret_cast<const float4*>(Rp + u * 28 + vg * 4);
                ull rd;
                rd = pk(rf.x, rf.x);
                acc[u][0] = f2fma(xq[0][0], rd, acc[u][0]);
                acc[u][1] = f2fma(xq[0][1], rd, acc[u][1]);
                rd = pk(rf.y, rf.y);
                acc[u][0] = f2fma(xq[1][0], rd, acc[u][0]);
                acc[u][1] = f2fma(xq[1][1], rd, acc[u][1]);
                rd = pk(rf.z, rf.z);
                acc[u][0] = f2fma(xq[2][0], rd, acc[u][0]);
                acc[u][1] = f2fma(xq[2][1], rd, acc[u][1]);
                rd = pk(rf.w, rf.w);
                acc[u][0] = f2fma(xq[3][0], rd, acc[u][0]);
                acc[u][1] = f2fma(xq[3][1], rd, acc[u][1]);
            }
        }
        // tail v = 24
        {
            float a0 = xs[tid * 25 + 24];
            float a1 = xs[(tid + 64) * 25 + 24];
            float a2 = xs[(tid + 128) * 25 + 24];
            float a3 = xs[(tid + 192) * 25 + 24];
            ull x0 = pk(a0, a1), x1 = pk(a2, a3);
            #pragma unroll
            for (int u = 0; u < 25; ++u) {
                float rv = Rp[u * 28 + 24];
                ull rd = pk(rv, rv);
                acc[u][0] = f2fma(x0, rd, acc[u][0]);
                acc[u][1] = f2fma(x1, rd, acc[u][1]);
            }
        }
    }

    // unpack + thread-local stats + stage into xs
    float sum = 0.f, sq = 0.f;
    __syncthreads();
    #pragma unroll
    for (int u = 0; u < 25; ++u) {
        float z0, z1, z2, z3;
        upk(z0, z1, acc[u][0]);
        upk(z2, z3, acc[u][1]);
        xs[tid * 25 + u]         = z0;
        xs[(tid + 64) * 25 + u]  = z1;
        xs[(tid + 128) * 25 + u] = z2;
        xs[(tid + 192) * 25 + u] = z3;
        sum += z0 + z1 + z2 + z3;
        sq  = fmaf(z0, z0, sq); sq = fmaf(z1, z1, sq);
        sq  = fmaf(z2, z2, sq); sq = fmaf(z3, z3, sq);
    }
    rs[tid] = sum; rq[tid] = sq;
    __syncthreads();
    {
        float4* outp = reinterpret_cast<float4*>(ybuf + ((size_t)(n * O + o)) * 6400);
        const float4* sp = reinterpret_cast<const float4*>(xs);
        for (int i = tid; i < 1600; i += 64) outp[i] = sp[i];
    }
    for (int st = 32; st > 0; st >>= 1) {
        if (tid < st) { rs[tid] += rs[tid + st]; rq[tid] += rq[tid + st]; }
        __syncthreads();
    }
    if (tid == 0) g_part2[o * NB + n] = make_float2(rs[0], rq[0]);
}

// ---------------- K5: BN stats combine ----------------
__global__ void k_stats2(const float* __restrict__ bnw, const float* __restrict__ bnb)
{
    int o = threadIdx.x;
    float s = 0.f, s2 = 0.f;
    for (int nn = 0; nn < NB; ++nn) {
        float2 p = g_part2[o * NB + nn];
        s += p.x; s2 += p.y;
    }
    float M = (float)(NB * T * V);
    float mean = s / M;
    float var  = s2 / M - mean * mean;
    float sc = bnw[o] * rsqrtf(var + 1e-5f);
    g_stats[o] = make_float2(sc, bnb[o] - mean * sc);
}

// ---------------- K6: BN apply + residual + relu ----------------
__global__ void k_final(float4* __restrict__ ybuf, const float4* __restrict__ x)
{
    int idx = blockIdx.x * 256 + threadIdx.x;
    int o = (idx / (T * V / 4)) & 63;
    float2 ss = g_stats[o];
    float4 y = ybuf[idx], xx = x[idx];
    y.x = fmaxf(fmaf(y.x, ss.x, ss.y) + xx.x, 0.f);
    y.y = fmaxf(fmaf(y.y, ss.x, ss.y) + xx.y, 0.f);
    y.z = fmaxf(fmaf(y.z, ss.x, ss.y) + xx.z, 0.f);
    y.w = fmaxf(fmaf(y.w, ss.x, ss.y) + xx.w, 0.f);
    ybuf[idx] = y;
}

// ---------------- launch ----------------
extern "C" void kernel_launch(void* const* d_in, const int* in_sizes, int n_in,
                              void* d_out, int out_size)
{
    (void)in_sizes; (void)n_in; (void)out_size;
    const float* x    = (const float*)d_in[0];
    const float* A    = (const float*)d_in[1];
    const float* alph = (const float*)d_in[2];
    const float* w1   = (const float*)d_in[3];
    const float* b1   = (const float*)d_in[4];
    const float* w2   = (const float*)d_in[5];
    const float* b2   = (const float*)d_in[6];
    const float* w3   = (const float*)d_in[7];
    const float* b3   = (const float*)d_in[8];
    const float* w4   = (const float*)d_in[9];
    const float* b4   = (const float*)d_in[10];
    const float* pw1  = (const float*)d_in[11];
    const float* pb1  = (const float*)d_in[12];
    const float* pw2  = (const float*)d_in[13];
    const float* pb2  = (const float*)d_in[14];
    const float* dww  = (const float*)d_in[15];
    const float* pjw  = (const float*)d_in[16];
    const float* beta = (const float*)d_in[17];
    const float* gamma= (const float*)d_in[18];
    const float* bnw  = (const float*)d_in[19];
    const float* bnb  = (const float*)d_in[20];
    float* out = (float*)d_out;

    cudaFuncSetAttribute(k_R,   cudaFuncAttributeMaxDynamicSharedMemorySize, 15800 * 4);
    cudaFuncSetAttribute(k_x3m, cudaFuncAttributeMaxDynamicSharedMemorySize, SM_TOT);
    cudaFuncSetAttribute(k_y,   cudaFuncAttributeMaxDynamicSharedMemorySize, KY_SMEM_B);

    k_wb<<<S * O * C / 256, 256>>>(w3);
    k_xm<<<NB * C, 256>>>(x);
    k_R<<<dim3(NB, S), 512, 15800 * 4>>>(A, alph, w1, b1, w2, b2, w4, b4,
                                         pw1, pb1, pw2, pb2, dww, pjw, beta, gamma);
    k_x3m<<<dim3(100, NB), 384, SM_TOT>>>(x, b3);
    k_y<<<dim3(O, NB), 64, KY_SMEM_B>>>(out);
    k_stats2<<<1, O>>>(bnw, bnb);
    k_final<<<(NB * C * T * V) / 1024, 256>>>((float4*)out, (const float4*)x);
}